// round 13
// baseline (speedup 1.0000x reference)
#include <cuda_runtime.h>
#include <cuda_bf16.h>
#include <math.h>

// Problem constants
#define NB    4
#define CIN   64
#define HIN   48
#define WIN   48
#define COUT  64
#define CM    32
#define HH    96
#define WW    96
#define LTOK  (HH*WW)     // 9216
#define NHASH 4
#define BUCK  64
#define CHUNK 144
#define KCHUNKS (LTOK/CHUNK)   // 64
#define TOTCODE 256
#define LSORT (NHASH*LTOK)     // 36864
#define FULLMASK 0xffffffffu

typedef unsigned long long ull;

// ---------------- f32x2 packed-math helpers (exact fp32, 2x throughput) ------
__device__ __forceinline__ ull pk2(float lo, float hi) {
    ull r; asm("mov.b64 %0, {%1, %2};" : "=l"(r) : "f"(lo), "f"(hi)); return r;
}
__device__ __forceinline__ void upk2(ull v, float& lo, float& hi) {
    asm("mov.b64 {%0, %1}, %2;" : "=f"(lo), "=f"(hi) : "l"(v));
}
__device__ __forceinline__ ull ffma2(ull a, ull b, ull c) {
    ull d; asm("fma.rn.f32x2 %0, %1, %2, %3;" : "=l"(d) : "l"(a), "l"(b), "l"(c)); return d;
}
__device__ __forceinline__ ull fmul2(ull a, ull b) {
    ull d; asm("mul.rn.f32x2 %0, %1, %2;" : "=l"(d) : "l"(a), "l"(b)); return d;
}

// ---------------- cp.async helpers ----------------
__device__ __forceinline__ void cpa4(unsigned dst, const float* src, bool p) {
    asm volatile("cp.async.ca.shared.global [%0], [%1], 4, %2;"
                 :: "r"(dst), "l"(src), "r"(p ? 4 : 0));
}
__device__ __forceinline__ void cpa_commit() {
    asm volatile("cp.async.commit_group;");
}
__device__ __forceinline__ void cpa_wait0() {
    asm volatile("cp.async.wait_group 0;");
}

// ---------------- device scratch ----------------
__device__ float g_up [NB*CIN*HH*WW];
__device__ float g_c1 [NB*COUT*HH*WW];
__device__ float g_c2 [NB*COUT*HH*WW];
__device__ float g_xe [NB*LTOK*CM];
__device__ float g_ye [NB*LTOK*COUT];
__device__ int   g_codes[NB*NHASH*LTOK];
__device__ int   g_hist [NB*TOTCODE];
__device__ int   g_pref [NB*TOTCODE];
__device__ int   g_sorted[NB*LSORT];
__device__ float g_ret [NB*NHASH*LTOK*COUT];
__device__ float g_bs  [NB*NHASH*LTOK];

// ---------------- bicubic upsample ----------------
__device__ __forceinline__ float keysk(float x) {
    x = fabsf(x);
    if (x <= 1.f) return (1.5f*x - 2.5f)*x*x + 1.f;
    if (x <  2.f) return ((-0.5f*x + 2.5f)*x - 4.f)*x + 2.f;
    return 0.f;
}

__global__ void upsample_kernel(const float* __restrict__ in, float* __restrict__ out) {
    int g = blockIdx.x*256 + threadIdx.x;
    if (g >= NB*CIN*HH*WW) return;
    int ox = g % WW, oy = (g/WW) % HH, bc = g/(HH*WW);
    float sy = 0.5f*oy - 0.25f;
    float sx = 0.5f*ox - 0.25f;
    int iy0 = (int)floorf(sy) - 1;
    int ix0 = (int)floorf(sx) - 1;
    float wy[4], wx[4]; int iy[4], ix[4];
    float sumy = 0.f, sumx = 0.f;
#pragma unroll
    for (int j = 0; j < 4; j++) {
        int y = iy0 + j, x = ix0 + j;
        float wyv = (y >= 0 && y < HIN) ? keysk(sy - (float)y) : 0.f;
        float wxv = (x >= 0 && x < WIN) ? keysk(sx - (float)x) : 0.f;
        iy[j] = min(max(y,0), HIN-1); ix[j] = min(max(x,0), WIN-1);
        wy[j] = wyv; wx[j] = wxv; sumy += wyv; sumx += wxv;
    }
    float inv = 1.f/(sumy*sumx);
    const float* inp = in + (size_t)bc*HIN*WIN;
    float acc = 0.f;
#pragma unroll
    for (int jy = 0; jy < 4; jy++) {
        float row = 0.f;
#pragma unroll
        for (int jx = 0; jx < 4; jx++) row += wx[jx]*inp[iy[jy]*WIN + ix[jx]];
        acc += wy[jy]*row;
    }
    out[g] = acc*inv;
}

// -- 3x3 conv: 32x32 tile, 2x2 px/thread, 8 couts/block, cp.async pipeline ---
#define STG   (4*1156)      // floats per input stage (4 channels of 34x34)
#define WSTG  (4*8*9)       // weight floats per stage (288)

__global__ void __launch_bounds__(256, 2) conv3x3_kernel(
    const float* __restrict__ in, const float* __restrict__ w,
    const float* __restrict__ bias, float* __restrict__ out,
    int CIN_, int COUT_, int relu, int token_major) {
    const int CPB = 8;
    int groups = COUT_/CPB;
    int z  = blockIdx.z;
    int cg = z % groups;
    int b  = z / groups;
    int tid = threadIdx.x;
    int tx = tid & 15, ty = tid >> 4;
    int ox0 = blockIdx.x*32, oy0 = blockIdx.y*32;
    __shared__ float s_in[2][STG];
    __shared__ float s_w[2][WSTG];
    unsigned u_in = (unsigned)__cvta_generic_to_shared(&s_in[0][0]);
    unsigned u_w  = (unsigned)__cvta_generic_to_shared(&s_w[0][0]);

    // per-thread load slots (offset within batch-base; -1 = zero-fill)
    int offs[19];
#pragma unroll
    for (int k2 = 0; k2 < 19; k2++) {
        int e = tid + k2*256;
        bool slot = (k2 < 18) || (tid < 16);
        int ch = e/1156, idx = e - ch*1156;
        int ly = idx/34, lx = idx - ly*34;
        int iy = oy0-1+ly, ix = ox0-1+lx;
        bool ok = slot && iy >= 0 && iy < HH && ix >= 0 && ix < WW;
        offs[k2] = ok ? (ch*HH*WW + iy*WW + ix) : -1;
    }
    int wb0, wb1;
    {
        int e = tid;
        int ch = e/72, rem = e - ch*72, co = rem/9, kk = rem - co*9;
        wb0 = ((cg*CPB+co)*CIN_ + ch)*9 + kk;
        e = 256 + tid;
        ch = e/72; rem = e - ch*72; co = rem/9; kk = rem - co*9;
        wb1 = ((cg*CPB+co)*CIN_ + ch)*9 + kk;
    }
    const float* inb = in + (size_t)b*CIN_*HH*WW;

    float acc[CPB][4];
#pragma unroll
    for (int i = 0; i < CPB; i++)
#pragma unroll
        for (int p = 0; p < 4; p++) acc[i][p] = 0.f;

    // stage loader via cp.async (zero-fills out-of-range via src-size=0)
    auto load_stage = [&](int s, int buf) {
        const float* inps = inb + (size_t)s*HH*WW;
        unsigned dbase = u_in + buf*STG*4;
#pragma unroll
        for (int k2 = 0; k2 < 18; k2++)
            cpa4(dbase + (tid + k2*256)*4,
                 inps + (offs[k2] >= 0 ? offs[k2] : 0), offs[k2] >= 0);
        if (tid < 16)
            cpa4(dbase + (4608+tid)*4,
                 inps + (offs[18] >= 0 ? offs[18] : 0), offs[18] >= 0);
        unsigned wbase = u_w + buf*WSTG*4;
        cpa4(wbase + tid*4, w + wb0 + s*9, true);
        if (tid < 32) cpa4(wbase + (256+tid)*4, w + wb1 + s*9, true);
    };

    load_stage(0, 0);
    cpa_commit();
    cpa_wait0();
    __syncthreads();

    for (int s = 0; s < CIN_; s += 4) {
        int cur = (s >> 2) & 1;
        bool more = (s + 4 < CIN_);
        if (more) { load_stage(s+4, cur^1); cpa_commit(); }
        // compute current stage
#pragma unroll
        for (int ch = 0; ch < 4; ch++) {
            float win[4][4];
            const float* base = s_in[cur] + ch*1156 + (2*ty)*34 + 2*tx;
#pragma unroll
            for (int rr = 0; rr < 4; rr++) {
                float2 a = *(const float2*)(base + rr*34);
                float2 bq = *(const float2*)(base + rr*34 + 2);
                win[rr][0] = a.x; win[rr][1] = a.y; win[rr][2] = bq.x; win[rr][3] = bq.y;
            }
            const float* wp = s_w[cur] + ch*CPB*9;
#pragma unroll
            for (int co = 0; co < CPB; co++) {
                float wr[9];
#pragma unroll
                for (int kk = 0; kk < 9; kk++) wr[kk] = wp[co*9+kk];
#pragma unroll
                for (int rr = 0; rr < 2; rr++)
#pragma unroll
                    for (int c = 0; c < 2; c++) {
                        float a = acc[co][rr*2+c];
#pragma unroll
                        for (int ky = 0; ky < 3; ky++)
#pragma unroll
                            for (int kx = 0; kx < 3; kx++)
                                a = fmaf(win[rr+ky][c+kx], wr[ky*3+kx], a);
                        acc[co][rr*2+c] = a;
                    }
            }
        }
        if (more) cpa_wait0();
        __syncthreads();
    }
#pragma unroll
    for (int co = 0; co < CPB; co++) {
        int cout = cg*CPB + co;
        float bv = bias[cout];
#pragma unroll
        for (int rr = 0; rr < 2; rr++) {
            float v0 = acc[co][rr*2+0] + bv;
            float v1 = acc[co][rr*2+1] + bv;
            if (relu) { v0 = fmaxf(v0, 0.f); v1 = fmaxf(v1, 0.f); }
            int row = oy0 + 2*ty + rr, col = ox0 + 2*tx;
            if (token_major) {
                out[((size_t)b*LTOK + row*WW + col    )*COUT_ + cout] = v0;
                out[((size_t)b*LTOK + row*WW + col + 1)*COUT_ + cout] = v1;
            } else {
                *(float2*)&out[((size_t)(b*COUT_+cout))*LTOK + row*WW + col] =
                    make_float2(v0, v1);
            }
        }
    }
}

// ---------------- 1x1 conv -> y_embed [b][t][64] --------------------------
__global__ void conv1x1_kernel(const float* __restrict__ in, const float* __restrict__ w,
                               const float* __restrict__ bias, float* __restrict__ out) {
    int b  = blockIdx.y;
    int t0 = blockIdx.x*64;
    __shared__ float s_x[64][65];
    __shared__ float s_w[64][65];
    int tid = threadIdx.x;
    for (int e = tid; e < 64*64; e += 256) {
        int ci = e >> 6, tt = e & 63;
        s_x[ci][tt] = in[((size_t)(b*COUT+ci))*LTOK + t0 + tt];
        int co = e & 63, ci2 = e >> 6;
        s_w[ci2][co] = w[co*64 + ci2];
    }
    __syncthreads();
    int co = tid & 63;
    int ts = tid >> 6;
    for (int tt = ts; tt < 64; tt += 4) {
        float a = bias[co];
#pragma unroll
        for (int ci = 0; ci < 64; ci++) a = fmaf(s_x[ci][tt], s_w[ci][co], a);
        out[((size_t)b*LTOK + t0 + tt)*COUT + co] = a;
    }
}

// ---------------- LSH hashing (f32x2 packed over bucket pairs) --------------
__global__ void hash_kernel(const float* __restrict__ xe, const float* __restrict__ rot,
                            int* __restrict__ codes) {
    __shared__ __align__(16) float s_rot[CM*NHASH*32];
    int tid = threadIdx.x;
    for (int e = tid; e < CM*NHASH*32; e += 128) s_rot[e] = rot[e];
    __syncthreads();
    int g = blockIdx.x*128 + tid;
    float xf[CM];
    const float* xp = xe + (size_t)g*CM;
#pragma unroll
    for (int f = 0; f < CM; f++) xf[f] = xp[f];
    int b = g / LTOK, t = g % LTOK;
    for (int h = 0; h < NHASH; h++) {
        ull acc2[16];
#pragma unroll
        for (int i = 0; i < 16; i++) acc2[i] = 0ull;
#pragma unroll 4
        for (int f = 0; f < CM; f++) {
            ull x2 = pk2(xf[f], xf[f]);
            const ull* rp = (const ull*)&s_rot[(f*NHASH + h)*32];
#pragma unroll
            for (int i = 0; i < 16; i++) acc2[i] = ffma2(x2, rp[i], acc2[i]);
        }
        float sv[32];
#pragma unroll
        for (int i = 0; i < 16; i++) upk2(acc2[i], sv[2*i], sv[2*i+1]);
        float bv = sv[0]; int bi = 0;
#pragma unroll
        for (int i = 1; i < 32; i++) if (sv[i] > bv) { bv = sv[i]; bi = i; }
#pragma unroll
        for (int i = 0; i < 32; i++) if (-sv[i] > bv) { bv = -sv[i]; bi = 32 + i; }
        codes[((size_t)(b*NHASH + h))*LTOK + t] = h*BUCK + bi;
    }
}

// ---------------- counting sort ----------------
__global__ void zero_hist_kernel(int* h) { h[blockIdx.x*256 + threadIdx.x] = 0; }

__global__ void hist_kernel(const int* __restrict__ codes, int* __restrict__ hist) {
    int g = blockIdx.x*256 + threadIdx.x;
    if (g < NB*LSORT) {
        int b = g / LSORT;
        atomicAdd(&hist[b*TOTCODE + codes[g]], 1);
    }
}

__global__ void prefix_kernel(const int* __restrict__ hist, int* __restrict__ pref) {
    int b = threadIdx.x;
    if (b < NB) {
        int s = 0;
        for (int c = 0; c < TOTCODE; c++) { pref[b*TOTCODE + c] = s; s += hist[b*TOTCODE + c]; }
    }
}

__global__ void scatter_kernel(const int* __restrict__ codes, const int* __restrict__ pref,
                               int* __restrict__ sorted_p) {
    int wid  = (blockIdx.x*blockDim.x + threadIdx.x) >> 5;
    int lane = threadIdx.x & 31;
    if (wid >= NB*TOTCODE) return;
    int b = wid >> 8, c = wid & 255;
    int h = c >> 6;
    int base = pref[b*TOTCODE + c];
    const int* cp = codes + ((size_t)(b*NHASH + h))*LTOK;
    int off = 0;
    for (int t0 = 0; t0 < LTOK; t0 += 32) {
        int t = t0 + lane;
        bool m = (cp[t] == c);
        unsigned mask = __ballot_sync(FULLMASK, m);
        if (m) {
            int pos = base + off + __popc(mask & ((1u << lane) - 1u));
            sorted_p[(size_t)b*LSORT + pos] = h*LTOK + t;
        }
        off += __popc(mask);
    }
}

// ---- chunked attention: f32x2 packed math, fused key-load+normalize --------
// smem: KT[32*144] | QT[32*144] | Y[144*64] | P2[18][48][4]float2 | tq
#define ATTN_SMEM ((32*144*2 + 144*64)*4 + 18*48*4*8 + 144*4)

__device__ __forceinline__ float gmax16(float v) {
    v = fmaxf(v, __shfl_xor_sync(FULLMASK, v, 1));
    v = fmaxf(v, __shfl_xor_sync(FULLMASK, v, 2));
    v = fmaxf(v, __shfl_xor_sync(FULLMASK, v, 4));
    v = fmaxf(v, __shfl_xor_sync(FULLMASK, v, 8));
    return v;
}
__device__ __forceinline__ float gsum16(float v) {
    v += __shfl_xor_sync(FULLMASK, v, 1);
    v += __shfl_xor_sync(FULLMASK, v, 2);
    v += __shfl_xor_sync(FULLMASK, v, 4);
    v += __shfl_xor_sync(FULLMASK, v, 8);
    return v;
}

__global__ void __launch_bounds__(288, 2) attn_kernel(
    const float* __restrict__ xe, const float* __restrict__ ye,
    const int* __restrict__ sorted_p, float* __restrict__ ret, float* __restrict__ bs) {
    extern __shared__ float sm[];
    float*  s_KT = sm;                   // [32][144] normalized keys
    float*  s_QT = s_KT + 32*144;        // [32][144]
    float*  s_Y  = s_QT + 32*144;        // [144][64]
    float2* s_P2 = (float2*)(s_Y + 144*64);   // [18][48][4] row-pair dups
    int*    s_tq = (int*)(s_P2 + 18*48*4);

    int blk = blockIdx.x;
    int k = blk & 63, h = (blk >> 6) & 3, b = blk >> 8;
    int tid = threadIdx.x;
    int tx = tid & 15, ty = tid >> 4;    // ty 0..17
    int r0 = ty*8, c0 = tx*4, jbase = tx*3;
    const int* spb = sorted_p + (size_t)b*LSORT + h*LTOK;

    if (tid < 144)
        s_tq[tid] = spb[k*CHUNK + tid] - h*LTOK;
    __syncthreads();
    for (int e = tid; e < 144*8; e += 288) {     // Q transposed, f-major
        int j = e >> 3, q = e & 7;
        float4 v = *(const float4*)(xe + ((size_t)b*LTOK + s_tq[j])*CM + q*4);
        s_QT[(q*4+0)*144 + j] = v.x; s_QT[(q*4+1)*144 + j] = v.y;
        s_QT[(q*4+2)*144 + j] = v.z; s_QT[(q*4+3)*144 + j] = v.w;
    }

    float m[8], s[8];
    ull o2[4][4];                         // o2[pair][c] = (row 2p, row 2p+1)
#pragma unroll
    for (int i = 0; i < 8; i++) { m[i] = -1e30f; s[i] = 0.f; }
#pragma unroll
    for (int p = 0; p < 4; p++)
#pragma unroll
        for (int c = 0; c < 4; c++) o2[p][c] = 0ull;

#pragma unroll 1
    for (int cc = 0; cc < 3; cc++) {
        int kc = (cc == 0) ? k : (cc == 1 ? (k + KCHUNKS - 1) % KCHUNKS
                                          : (k + 1) % KCHUNKS);
        __syncthreads();
        if (tid < 144) {
            // one thread = one key column: load, normalize in regs, store transposed
            int tok = spb[kc*CHUNK + tid] - h*LTOK;
            const float* xp = xe + ((size_t)b*LTOK + tok)*CM;
            float v[32]; float ss = 0.f;
#pragma unroll
            for (int q = 0; q < 8; q++) {
                float4 t4 = *(const float4*)(xp + q*4);
                v[q*4+0] = t4.x; v[q*4+1] = t4.y; v[q*4+2] = t4.z; v[q*4+3] = t4.w;
            }
#pragma unroll
            for (int f = 0; f < 32; f++) ss = fmaf(v[f], v[f], ss);
            float inv = 1.f / fmaxf(sqrtf(ss), 5e-5f);
#pragma unroll
            for (int f = 0; f < 32; f++) s_KT[f*144 + tid] = v[f]*inv;
        } else {
            // other 144 threads load Y concurrently
            for (int e = tid - 144; e < 144*16; e += 144) {
                int j = e >> 4, q = e & 15;
                int tok = spb[kc*CHUNK + j] - h*LTOK;
                float4 vv = *(const float4*)(ye + ((size_t)b*LTOK + tok)*COUT + q*4);
                *(float4*)(s_Y + j*64 + q*4) = vv;
            }
        }
        __syncthreads();

#pragma unroll 1
        for (int w = 0; w < 3; w++) {               // 48-key windows
            int kw0 = w*48;
            // GEMM1: packed S(4 pairs x 3 keys)
            ull acc2[4][3];
#pragma unroll
            for (int p = 0; p < 4; p++)
#pragma unroll
                for (int j = 0; j < 3; j++) acc2[p][j] = 0ull;
#pragma unroll 2
            for (int f = 0; f < 32; f++) {
                ull qv[4];
#pragma unroll
                for (int p = 0; p < 4; p++)
                    qv[p] = *(const ull*)(s_QT + f*144 + r0 + 2*p);
#pragma unroll
                for (int j = 0; j < 3; j++) {
                    float kv = s_KT[f*144 + kw0 + jbase + j];
                    ull k2 = pk2(kv, kv);
#pragma unroll
                    for (int p = 0; p < 4; p++)
                        acc2[p][j] = ffma2(qv[p], k2, acc2[p][j]);
                }
            }
            // unpack scores
            float a[8][3];
#pragma unroll
            for (int p = 0; p < 4; p++)
#pragma unroll
                for (int j = 0; j < 3; j++) upk2(acc2[p][j], a[2*p][j], a[2*p+1][j]);
            // online softmax per row (half-warp reduce)
            float fct[8];
#pragma unroll
            for (int i = 0; i < 8; i++) {
                float mx = fmaxf(fmaxf(a[i][0], a[i][1]), a[i][2]);
                mx = gmax16(mx);
                float mnew = fmaxf(m[i], mx);
                fct[i] = __expf(m[i] - mnew);
                float sum = 0.f;
#pragma unroll
                for (int j = 0; j < 3; j++) {
                    float pv = __expf(a[i][j] - mnew);
                    a[i][j] = pv; sum += pv;
                }
                s[i] = s[i]*fct[i] + gsum16(sum);
                m[i] = mnew;
            }
            __syncwarp();          // prior window's P reads complete
#pragma unroll
            for (int j = 0; j < 3; j++)
#pragma unroll
                for (int p = 0; p < 4; p++)
                    s_P2[(ty*48 + jbase + j)*4 + p] = make_float2(a[2*p][j], a[2*p+1][j]);
            // rescale O (packed)
#pragma unroll
            for (int p = 0; p < 4; p++) {
                ull f2 = pk2(fct[2*p], fct[2*p+1]);
#pragma unroll
                for (int c = 0; c < 4; c++) o2[p][c] = fmul2(o2[p][c], f2);
            }
            __syncwarp();          // P visible to half-warp
            // GEMM2: O += P*Y (packed over row pairs)
#pragma unroll 2
            for (int key = 0; key < 48; key++) {
                float4 y = *(const float4*)(s_Y + (kw0 + key)*64 + c0);
                ull yd[4] = { pk2(y.x,y.x), pk2(y.y,y.y), pk2(y.z,y.z), pk2(y.w,y.w) };
                const ull* pp = (const ull*)&s_P2[(ty*48 + key)*4];
#pragma unroll
                for (int p = 0; p < 4; p++) {
                    ull pv = pp[p];
#pragma unroll
                    for (int c = 0; c < 4; c++)
                        o2[p][c] = ffma2(pv, yd[c], o2[p][c]);
                }
            }
        }
    }

    // epilogue
#pragma unroll
    for (int p = 0; p < 4; p++) {
        float lo[4], hi[4];
#pragma unroll
        for (int c = 0; c < 4; c++) upk2(o2[p][c], lo[c], hi[c]);
        float inv0 = 1.f / s[2*p], inv1 = 1.f / s[2*p+1];
        *(float4*)(ret + (((size_t)(b*NHASH + h))*LTOK + s_tq[r0+2*p  ])*COUT + c0) =
            make_float4(lo[0]*inv0, lo[1]*inv0, lo[2]*inv0, lo[3]*inv0);
        *(float4*)(ret + (((size_t)(b*NHASH + h))*LTOK + s_tq[r0+2*p+1])*COUT + c0) =
            make_float4(hi[0]*inv1, hi[1]*inv1, hi[2]*inv1, hi[3]*inv1);
    }
    if (tx == 0) {
#pragma unroll
        for (int i = 0; i < 8; i++)
            bs[((size_t)(b*NHASH + h))*LTOK + s_tq[r0+i]] = m[i] + __logf(s[i]);
    }
}

// ---------------- combine hash rounds + residual ---------------------------
__global__ void combine_kernel(const float* __restrict__ ret, const float* __restrict__ bs,
                               const float* __restrict__ resid, float* __restrict__ out) {
    int b = blockIdx.y, t0 = blockIdx.x*32;
    __shared__ float s_p[NHASH][32];
    __shared__ float s_tile[64][33];
    int tid = threadIdx.x;
    if (tid < 32) {
        int t = t0 + tid;
        float v0 = bs[((size_t)(b*NHASH+0))*LTOK + t];
        float v1 = bs[((size_t)(b*NHASH+1))*LTOK + t];
        float v2 = bs[((size_t)(b*NHASH+2))*LTOK + t];
        float v3 = bs[((size_t)(b*NHASH+3))*LTOK + t];
        float mm = fmaxf(fmaxf(v0,v1), fmaxf(v2,v3));
        float p0 = __expf(v0-mm), p1 = __expf(v1-mm), p2 = __expf(v2-mm), p3 = __expf(v3-mm);
        float inv = 1.f/(p0+p1+p2+p3);
        s_p[0][tid] = p0*inv; s_p[1][tid] = p1*inv; s_p[2][tid] = p2*inv; s_p[3][tid] = p3*inv;
    }
    __syncthreads();
    for (int e = tid; e < 2048; e += 256) {
        int c = e & 63, tl = e >> 6;
        int t = t0 + tl;
        float a = 0.f;
#pragma unroll
        for (int h = 0; h < NHASH; h++)
            a = fmaf(s_p[h][tl], ret[(((size_t)(b*NHASH + h))*LTOK + t)*COUT + c], a);
        s_tile[c][tl] = a;
    }
    __syncthreads();
    for (int e = tid; e < 2048; e += 256) {
        int tl = e & 31, c = e >> 5;
        size_t idx = ((size_t)(b*COUT + c))*LTOK + t0 + tl;
        out[idx] = s_tile[c][tl] + resid[idx];
    }
}

// ---------------- launch -----------------------------------------------------
extern "C" void kernel_launch(void* const* d_in, const int* in_sizes, int n_in,
                              void* d_out, int out_size) {
    const float* x   = (const float*)d_in[0];
    const float* w1  = (const float*)d_in[1];
    const float* b1  = (const float*)d_in[2];
    const float* w2  = (const float*)d_in[3];
    const float* b2  = (const float*)d_in[4];
    const float* wm  = (const float*)d_in[5];
    const float* bm  = (const float*)d_in[6];
    const float* wa  = (const float*)d_in[7];
    const float* ba  = (const float*)d_in[8];
    const float* rot = (const float*)d_in[9];
    float* out = (float*)d_out;

    float *up, *c1, *c2, *xe, *ye, *ret, *bsp;
    int *codes, *hist, *pref, *sorted;
    cudaGetSymbolAddress((void**)&up,    g_up);
    cudaGetSymbolAddress((void**)&c1,    g_c1);
    cudaGetSymbolAddress((void**)&c2,    g_c2);
    cudaGetSymbolAddress((void**)&xe,    g_xe);
    cudaGetSymbolAddress((void**)&ye,    g_ye);
    cudaGetSymbolAddress((void**)&ret,   g_ret);
    cudaGetSymbolAddress((void**)&bsp,   g_bs);
    cudaGetSymbolAddress((void**)&codes, g_codes);
    cudaGetSymbolAddress((void**)&hist,  g_hist);
    cudaGetSymbolAddress((void**)&pref,  g_pref);
    cudaGetSymbolAddress((void**)&sorted,g_sorted);

    cudaFuncSetAttribute(attn_kernel, cudaFuncAttributeMaxDynamicSharedMemorySize, ATTN_SMEM);

    // 1. bicubic upsample
    upsample_kernel<<<(NB*CIN*HH*WW + 255)/256, 256>>>(x, up);
    // 2-3. conv3x3 + relu x2 (cp.async double-buffered)
    conv3x3_kernel<<<dim3(3,3,NB*8), 256>>>(up, w1, b1, c1, CIN,  COUT, 1, 0);
    conv3x3_kernel<<<dim3(3,3,NB*8), 256>>>(c1, w2, b2, c2, COUT, COUT, 1, 0);
    // 4. match conv -> x_embed token-major
    conv3x3_kernel<<<dim3(3,3,NB*4), 256>>>(c2, wm, bm, xe, COUT, CM, 0, 1);
    // 5. assembly 1x1 -> y_embed token-major
    conv1x1_kernel<<<dim3(LTOK/64, NB), 256>>>(c2, wa, ba, ye);
    // 6. LSH codes (packed)
    hash_kernel<<<NB*LTOK/128, 128>>>(xe, rot, codes);
    // 7. stable counting sort
    zero_hist_kernel<<<NB, 256>>>(hist);
    hist_kernel<<<(NB*LSORT + 255)/256, 256>>>(codes, hist);
    prefix_kernel<<<1, 32>>>(hist, pref);
    scatter_kernel<<<NB*TOTCODE/8, 256>>>(codes, pref, sorted);
    // 8. chunked attention (288 threads: 18 row-groups x 16 key-threads)
    attn_kernel<<<NB*NHASH*KCHUNKS, 288, ATTN_SMEM>>>(xe, ye, sorted, ret, bsp);
    // 9. combine hash rounds + residual
    combine_kernel<<<dim3(LTOK/32, NB), 256>>>(ret, bsp, c2, out);
}

// round 14
// speedup vs baseline: 1.0704x; 1.0704x over previous
#include <cuda_runtime.h>
#include <cuda_bf16.h>
#include <math.h>

// Problem constants
#define NB    4
#define CIN   64
#define HIN   48
#define WIN   48
#define COUT  64
#define CM    32
#define HH    96
#define WW    96
#define LTOK  (HH*WW)     // 9216
#define NHASH 4
#define BUCK  64
#define CHUNK 144
#define KCHUNKS (LTOK/CHUNK)   // 64
#define TOTCODE 256
#define LSORT (NHASH*LTOK)     // 36864
#define FULLMASK 0xffffffffu

typedef unsigned long long ull;

// ---------------- f32x2 packed-math helpers (exact fp32, 2x throughput) ------
__device__ __forceinline__ ull pk2(float lo, float hi) {
    ull r; asm("mov.b64 %0, {%1, %2};" : "=l"(r) : "f"(lo), "f"(hi)); return r;
}
__device__ __forceinline__ void upk2(ull v, float& lo, float& hi) {
    asm("mov.b64 {%0, %1}, %2;" : "=f"(lo), "=f"(hi) : "l"(v));
}
__device__ __forceinline__ ull ffma2(ull a, ull b, ull c) {
    ull d; asm("fma.rn.f32x2 %0, %1, %2, %3;" : "=l"(d) : "l"(a), "l"(b), "l"(c)); return d;
}

// ---------------- device scratch ----------------
__device__ float g_up [NB*CIN*HH*WW];
__device__ float g_c1 [NB*COUT*HH*WW];
__device__ float g_c2 [NB*COUT*HH*WW];
__device__ float g_xe [NB*LTOK*CM];
__device__ float g_ye [NB*LTOK*COUT];
__device__ int   g_codes[NB*NHASH*LTOK];
__device__ int   g_hist [NB*TOTCODE];
__device__ int   g_pref [NB*TOTCODE];
__device__ int   g_sorted[NB*LSORT];
__device__ float g_ret [NB*NHASH*LTOK*COUT];
__device__ float g_bs  [NB*NHASH*LTOK];

// ---------------- bicubic upsample ----------------
__device__ __forceinline__ float keysk(float x) {
    x = fabsf(x);
    if (x <= 1.f) return (1.5f*x - 2.5f)*x*x + 1.f;
    if (x <  2.f) return ((-0.5f*x + 2.5f)*x - 4.f)*x + 2.f;
    return 0.f;
}

__global__ void upsample_kernel(const float* __restrict__ in, float* __restrict__ out) {
    int g = blockIdx.x*256 + threadIdx.x;
    if (g >= NB*CIN*HH*WW) return;
    int ox = g % WW, oy = (g/WW) % HH, bc = g/(HH*WW);
    float sy = 0.5f*oy - 0.25f;
    float sx = 0.5f*ox - 0.25f;
    int iy0 = (int)floorf(sy) - 1;
    int ix0 = (int)floorf(sx) - 1;
    float wy[4], wx[4]; int iy[4], ix[4];
    float sumy = 0.f, sumx = 0.f;
#pragma unroll
    for (int j = 0; j < 4; j++) {
        int y = iy0 + j, x = ix0 + j;
        float wyv = (y >= 0 && y < HIN) ? keysk(sy - (float)y) : 0.f;
        float wxv = (x >= 0 && x < WIN) ? keysk(sx - (float)x) : 0.f;
        iy[j] = min(max(y,0), HIN-1); ix[j] = min(max(x,0), WIN-1);
        wy[j] = wyv; wx[j] = wxv; sumy += wyv; sumx += wxv;
    }
    float inv = 1.f/(sumy*sumx);
    const float* inp = in + (size_t)bc*HIN*WIN;
    float acc = 0.f;
#pragma unroll
    for (int jy = 0; jy < 4; jy++) {
        float row = 0.f;
#pragma unroll
        for (int jx = 0; jx < 4; jx++) row += wx[jx]*inp[iy[jy]*WIN + ix[jx]];
        acc += wy[jy]*row;
    }
    out[g] = acc*inv;
}

// -- 3x3 conv: 32x32 tile, 2x2 px/thread, 8 couts/block, double-buffered -----
#define STG   (4*1156)      // floats per input stage (4 channels of 34x34)
#define WSTG  (4*8*9)       // weight floats per stage (288)

__global__ void __launch_bounds__(256, 2) conv3x3_kernel(
    const float* __restrict__ in, const float* __restrict__ w,
    const float* __restrict__ bias, float* __restrict__ out,
    int CIN_, int COUT_, int relu, int token_major) {
    const int CPB = 8;
    int groups = COUT_/CPB;
    int z  = blockIdx.z;
    int cg = z % groups;
    int b  = z / groups;
    int tid = threadIdx.x;
    int tx = tid & 15, ty = tid >> 4;
    int ox0 = blockIdx.x*32, oy0 = blockIdx.y*32;
    __shared__ float s_in[2][STG];
    __shared__ float s_w[2][WSTG];

    // precompute per-thread load slots (offset within channel-base, -1 = zero)
    int offs[19];
#pragma unroll
    for (int k2 = 0; k2 < 19; k2++) {
        int e = tid + k2*256;
        bool slot = (k2 < 18) || (tid < 16);
        int ch = e/1156, idx = e - ch*1156;
        int ly = idx/34, lx = idx - ly*34;
        int iy = oy0-1+ly, ix = ox0-1+lx;
        bool ok = slot && iy >= 0 && iy < HH && ix >= 0 && ix < WW;
        offs[k2] = ok ? (ch*HH*WW + iy*WW + ix) : -1;
    }
    int wb0, wb1;
    {
        int e = tid;
        int ch = e/72, rem = e - ch*72, co = rem/9, kk = rem - co*9;
        wb0 = ((cg*CPB+co)*CIN_ + ch)*9 + kk;
        e = 256 + tid;
        ch = e/72; rem = e - ch*72; co = rem/9; kk = rem - co*9;
        wb1 = ((cg*CPB+co)*CIN_ + ch)*9 + kk;
    }
    const float* inb = in + (size_t)b*CIN_*HH*WW;

    float acc[CPB][4];
#pragma unroll
    for (int i = 0; i < CPB; i++)
#pragma unroll
        for (int p = 0; p < 4; p++) acc[i][p] = 0.f;

    // stage 0 load
    {
        const float* inps = inb;
#pragma unroll
        for (int k2 = 0; k2 < 18; k2++)
            s_in[0][tid + k2*256] = (offs[k2] >= 0) ? inps[offs[k2]] : 0.f;
        if (tid < 16) s_in[0][4608+tid] = (offs[18] >= 0) ? inps[offs[18]] : 0.f;
        s_w[0][tid] = w[wb0];
        if (tid < 32) s_w[0][256+tid] = w[wb1];
    }
    __syncthreads();

    for (int s = 0; s < CIN_; s += 4) {
        int cur = (s >> 2) & 1;
        // prefetch next stage into registers (overlaps with compute below)
        float r[19]; float rw0 = 0.f, rw1 = 0.f;
        bool more = (s + 4 < CIN_);
        if (more) {
            const float* inps = inb + (size_t)(s+4)*HH*WW;
#pragma unroll
            for (int k2 = 0; k2 < 19; k2++)
                r[k2] = (offs[k2] >= 0) ? inps[offs[k2]] : 0.f;
            rw0 = w[wb0 + (s+4)*9];
            if (tid < 32) rw1 = w[wb1 + (s+4)*9];
        }
        // compute current stage
#pragma unroll
        for (int ch = 0; ch < 4; ch++) {
            float win[4][4];
            const float* base = s_in[cur] + ch*1156 + (2*ty)*34 + 2*tx;
#pragma unroll
            for (int rr = 0; rr < 4; rr++) {
                float2 a = *(const float2*)(base + rr*34);
                float2 bq = *(const float2*)(base + rr*34 + 2);
                win[rr][0] = a.x; win[rr][1] = a.y; win[rr][2] = bq.x; win[rr][3] = bq.y;
            }
            const float* wp = s_w[cur] + ch*CPB*9;
#pragma unroll
            for (int co = 0; co < CPB; co++) {
                float wr[9];
#pragma unroll
                for (int kk = 0; kk < 9; kk++) wr[kk] = wp[co*9+kk];
#pragma unroll
                for (int rr = 0; rr < 2; rr++)
#pragma unroll
                    for (int c = 0; c < 2; c++) {
                        float a = acc[co][rr*2+c];
#pragma unroll
                        for (int ky = 0; ky < 3; ky++)
#pragma unroll
                            for (int kx = 0; kx < 3; kx++)
                                a = fmaf(win[rr+ky][c+kx], wr[ky*3+kx], a);
                        acc[co][rr*2+c] = a;
                    }
            }
        }
        // commit prefetched stage to alternate buffer
        if (more) {
            float* dst = s_in[cur^1];
#pragma unroll
            for (int k2 = 0; k2 < 18; k2++) dst[tid + k2*256] = r[k2];
            if (tid < 16) dst[4608+tid] = r[18];
            s_w[cur^1][tid] = rw0;
            if (tid < 32) s_w[cur^1][256+tid] = rw1;
        }
        __syncthreads();
    }
#pragma unroll
    for (int co = 0; co < CPB; co++) {
        int cout = cg*CPB + co;
        float bv = bias[cout];
#pragma unroll
        for (int rr = 0; rr < 2; rr++) {
            float v0 = acc[co][rr*2+0] + bv;
            float v1 = acc[co][rr*2+1] + bv;
            if (relu) { v0 = fmaxf(v0, 0.f); v1 = fmaxf(v1, 0.f); }
            int row = oy0 + 2*ty + rr, col = ox0 + 2*tx;
            if (token_major) {
                out[((size_t)b*LTOK + row*WW + col    )*COUT_ + cout] = v0;
                out[((size_t)b*LTOK + row*WW + col + 1)*COUT_ + cout] = v1;
            } else {
                *(float2*)&out[((size_t)(b*COUT_+cout))*LTOK + row*WW + col] =
                    make_float2(v0, v1);
            }
        }
    }
}

// ---------------- 1x1 conv -> y_embed [b][t][64] --------------------------
__global__ void conv1x1_kernel(const float* __restrict__ in, const float* __restrict__ w,
                               const float* __restrict__ bias, float* __restrict__ out) {
    int b  = blockIdx.y;
    int t0 = blockIdx.x*64;
    __shared__ float s_x[64][65];
    __shared__ float s_w[64][65];
    int tid = threadIdx.x;
    for (int e = tid; e < 64*64; e += 256) {
        int ci = e >> 6, tt = e & 63;
        s_x[ci][tt] = in[((size_t)(b*COUT+ci))*LTOK + t0 + tt];
        int co = e & 63, ci2 = e >> 6;
        s_w[ci2][co] = w[co*64 + ci2];
    }
    __syncthreads();
    int co = tid & 63;
    int ts = tid >> 6;
    for (int tt = ts; tt < 64; tt += 4) {
        float a = bias[co];
#pragma unroll
        for (int ci = 0; ci < 64; ci++) a = fmaf(s_x[ci][tt], s_w[ci][co], a);
        out[((size_t)b*LTOK + t0 + tt)*COUT + co] = a;
    }
}

// ---------------- LSH hashing (f32x2 packed over bucket pairs) --------------
__global__ void hash_kernel(const float* __restrict__ xe, const float* __restrict__ rot,
                            int* __restrict__ codes) {
    __shared__ __align__(16) float s_rot[CM*NHASH*32];
    int tid = threadIdx.x;
    for (int e = tid; e < CM*NHASH*32; e += 128) s_rot[e] = rot[e];
    __syncthreads();
    int g = blockIdx.x*128 + tid;
    float xf[CM];
    const float* xp = xe + (size_t)g*CM;
#pragma unroll
    for (int f = 0; f < CM; f++) xf[f] = xp[f];
    int b = g / LTOK, t = g % LTOK;
    for (int h = 0; h < NHASH; h++) {
        ull acc2[16];
#pragma unroll
        for (int i = 0; i < 16; i++) acc2[i] = 0ull;
#pragma unroll 4
        for (int f = 0; f < CM; f++) {
            ull x2 = pk2(xf[f], xf[f]);
            const ull* rp = (const ull*)&s_rot[(f*NHASH + h)*32];
#pragma unroll
            for (int i = 0; i < 16; i++) acc2[i] = ffma2(x2, rp[i], acc2[i]);
        }
        float sv[32];
#pragma unroll
        for (int i = 0; i < 16; i++) upk2(acc2[i], sv[2*i], sv[2*i+1]);
        float bv = sv[0]; int bi = 0;
#pragma unroll
        for (int i = 1; i < 32; i++) if (sv[i] > bv) { bv = sv[i]; bi = i; }
#pragma unroll
        for (int i = 0; i < 32; i++) if (-sv[i] > bv) { bv = -sv[i]; bi = 32 + i; }
        codes[((size_t)(b*NHASH + h))*LTOK + t] = h*BUCK + bi;
    }
}

// ---------------- counting sort ----------------
__global__ void zero_hist_kernel(int* h) { h[blockIdx.x*256 + threadIdx.x] = 0; }

__global__ void hist_kernel(const int* __restrict__ codes, int* __restrict__ hist) {
    int g = blockIdx.x*256 + threadIdx.x;
    if (g < NB*LSORT) {
        int b = g / LSORT;
        atomicAdd(&hist[b*TOTCODE + codes[g]], 1);
    }
}

__global__ void prefix_kernel(const int* __restrict__ hist, int* __restrict__ pref) {
    int b = threadIdx.x;
    if (b < NB) {
        int s = 0;
        for (int c = 0; c < TOTCODE; c++) { pref[b*TOTCODE + c] = s; s += hist[b*TOTCODE + c]; }
    }
}

__global__ void scatter_kernel(const int* __restrict__ codes, const int* __restrict__ pref,
                               int* __restrict__ sorted_p) {
    int wid  = (blockIdx.x*blockDim.x + threadIdx.x) >> 5;
    int lane = threadIdx.x & 31;
    if (wid >= NB*TOTCODE) return;
    int b = wid >> 8, c = wid & 255;
    int h = c >> 6;
    int base = pref[b*TOTCODE + c];
    const int* cp = codes + ((size_t)(b*NHASH + h))*LTOK;
    int off = 0;
    for (int t0 = 0; t0 < LTOK; t0 += 32) {
        int t = t0 + lane;
        bool m = (cp[t] == c);
        unsigned mask = __ballot_sync(FULLMASK, m);
        if (m) {
            int pos = base + off + __popc(mask & ((1u << lane) - 1u));
            sorted_p[(size_t)b*LSORT + pos] = h*LTOK + t;
        }
        off += __popc(mask);
    }
}

// ---- chunked attention: known softmax max (m = |q|, self-match) -------------
// smem: KT[32*144] | QT[32*144] | Y[144*64] | P2[18][48][4]float2 | tq | nrm
#define ATTN_SMEM ((32*144*2 + 144*64)*4 + 18*48*4*8 + 144*4 + 144*4)

__device__ __forceinline__ float gsum16(float v) {
    v += __shfl_xor_sync(FULLMASK, v, 1);
    v += __shfl_xor_sync(FULLMASK, v, 2);
    v += __shfl_xor_sync(FULLMASK, v, 4);
    v += __shfl_xor_sync(FULLMASK, v, 8);
    return v;
}

__global__ void __launch_bounds__(288, 2) attn_kernel(
    const float* __restrict__ xe, const float* __restrict__ ye,
    const int* __restrict__ sorted_p, float* __restrict__ ret, float* __restrict__ bs) {
    extern __shared__ float sm[];
    float*  s_KT = sm;                   // [32][144] normalized keys
    float*  s_QT = s_KT + 32*144;        // [32][144]
    float*  s_Y  = s_QT + 32*144;        // [144][64]
    float2* s_P2 = (float2*)(s_Y + 144*64);   // [18][48][4] row-pair dups
    int*    s_tq = (int*)(s_P2 + 18*48*4);
    float*  s_m  = (float*)(s_tq + 144);      // |q| per row

    int blk = blockIdx.x;
    int k = blk & 63, h = (blk >> 6) & 3, b = blk >> 8;
    int tid = threadIdx.x;
    int tx = tid & 15, ty = tid >> 4;    // ty 0..17
    int r0 = ty*8, c0 = tx*4, jbase = tx*3;
    const int* spb = sorted_p + (size_t)b*LSORT + h*LTOK;

    if (tid < 144)
        s_tq[tid] = spb[k*CHUNK + tid] - h*LTOK;
    __syncthreads();
    for (int e = tid; e < 144*8; e += 288) {     // Q transposed, f-major
        int j = e >> 3, q = e & 7;
        float4 v = *(const float4*)(xe + ((size_t)b*LTOK + s_tq[j])*CM + q*4);
        s_QT[(q*4+0)*144 + j] = v.x; s_QT[(q*4+1)*144 + j] = v.y;
        s_QT[(q*4+2)*144 + j] = v.z; s_QT[(q*4+3)*144 + j] = v.w;
    }

    float m[8], s[8];
    ull o2[4][4];                         // o2[pair][c] = (row 2p, row 2p+1)
#pragma unroll
    for (int i = 0; i < 8; i++) s[i] = 0.f;
#pragma unroll
    for (int p = 0; p < 4; p++)
#pragma unroll
        for (int c = 0; c < 4; c++) o2[p][c] = 0ull;

#pragma unroll 1
    for (int cc = 0; cc < 3; cc++) {
        int kc = (cc == 0) ? k : (cc == 1 ? (k + KCHUNKS - 1) % KCHUNKS
                                          : (k + 1) % KCHUNKS);
        __syncthreads();
        if (tid < 144) {
            // one thread = one key column: load, normalize in regs, store transposed
            int tok = spb[kc*CHUNK + tid] - h*LTOK;
            const float* xp = xe + ((size_t)b*LTOK + tok)*CM;
            float v[32]; float ss = 0.f;
#pragma unroll
            for (int q = 0; q < 8; q++) {
                float4 t4 = *(const float4*)(xp + q*4);
                v[q*4+0] = t4.x; v[q*4+1] = t4.y; v[q*4+2] = t4.z; v[q*4+3] = t4.w;
            }
#pragma unroll
            for (int f = 0; f < 32; f++) ss = fmaf(v[f], v[f], ss);
            float nrm = sqrtf(ss);
            if (cc == 0) s_m[tid] = nrm;   // chunk-0 keys ARE the queries: m = |q|
            float inv = 1.f / fmaxf(nrm, 5e-5f);
#pragma unroll
            for (int f = 0; f < 32; f++) s_KT[f*144 + tid] = v[f]*inv;
        } else {
            // other 144 threads load Y concurrently
            for (int e = tid - 144; e < 144*16; e += 144) {
                int j = e >> 4, q = e & 15;
                int tok = spb[kc*CHUNK + j] - h*LTOK;
                float4 vv = *(const float4*)(ye + ((size_t)b*LTOK + tok)*COUT + q*4);
                *(float4*)(s_Y + j*64 + q*4) = vv;
            }
        }
        __syncthreads();
        if (cc == 0) {
#pragma unroll
            for (int i = 0; i < 8; i++) m[i] = s_m[r0 + i];
        }

#pragma unroll 1
        for (int w = 0; w < 3; w++) {               // 48-key windows
            int kw0 = w*48;
            // GEMM1: packed S(4 pairs x 3 keys)
            ull acc2[4][3];
#pragma unroll
            for (int p = 0; p < 4; p++)
#pragma unroll
                for (int j = 0; j < 3; j++) acc2[p][j] = 0ull;
#pragma unroll 2
            for (int f = 0; f < 32; f++) {
                ull qv[4];
#pragma unroll
                for (int p = 0; p < 4; p++)
                    qv[p] = *(const ull*)(s_QT + f*144 + r0 + 2*p);
#pragma unroll
                for (int j = 0; j < 3; j++) {
                    float kv = s_KT[f*144 + kw0 + jbase + j];
                    ull k2 = pk2(kv, kv);
#pragma unroll
                    for (int p = 0; p < 4; p++)
                        acc2[p][j] = ffma2(qv[p], k2, acc2[p][j]);
                }
            }
            // softmax with known max: p = exp(s - |q|); no reductions, no rescale
            float a[8][3];
#pragma unroll
            for (int p = 0; p < 4; p++)
#pragma unroll
                for (int j = 0; j < 3; j++) upk2(acc2[p][j], a[2*p][j], a[2*p+1][j]);
#pragma unroll
            for (int i = 0; i < 8; i++) {
#pragma unroll
                for (int j = 0; j < 3; j++) {
                    float pv = __expf(a[i][j] - m[i]);
                    a[i][j] = pv; s[i] += pv;
                }
            }
            __syncwarp();          // prior window's P reads complete
#pragma unroll
            for (int j = 0; j < 3; j++)
#pragma unroll
                for (int p = 0; p < 4; p++)
                    s_P2[(ty*48 + jbase + j)*4 + p] = make_float2(a[2*p][j], a[2*p+1][j]);
            __syncwarp();          // P visible to half-warp
            // GEMM2: O += P*Y (packed over row pairs)
#pragma unroll 2
            for (int key = 0; key < 48; key++) {
                float4 y = *(const float4*)(s_Y + (kw0 + key)*64 + c0);
                ull yd[4] = { pk2(y.x,y.x), pk2(y.y,y.y), pk2(y.z,y.z), pk2(y.w,y.w) };
                const ull* pp = (const ull*)&s_P2[(ty*48 + key)*4];
#pragma unroll
                for (int p = 0; p < 4; p++) {
                    ull pv = pp[p];
#pragma unroll
                    for (int c = 0; c < 4; c++)
                        o2[p][c] = ffma2(pv, yd[c], o2[p][c]);
                }
            }
        }
    }

    // epilogue: single cross-thread sum reduction per row
#pragma unroll
    for (int i = 0; i < 8; i++) s[i] = gsum16(s[i]);
#pragma unroll
    for (int p = 0; p < 4; p++) {
        float lo[4], hi[4];
#pragma unroll
        for (int c = 0; c < 4; c++) upk2(o2[p][c], lo[c], hi[c]);
        float inv0 = 1.f / s[2*p], inv1 = 1.f / s[2*p+1];
        *(float4*)(ret + (((size_t)(b*NHASH + h))*LTOK + s_tq[r0+2*p  ])*COUT + c0) =
            make_float4(lo[0]*inv0, lo[1]*inv0, lo[2]*inv0, lo[3]*inv0);
        *(float4*)(ret + (((size_t)(b*NHASH + h))*LTOK + s_tq[r0+2*p+1])*COUT + c0) =
            make_float4(hi[0]*inv1, hi[1]*inv1, hi[2]*inv1, hi[3]*inv1);
    }
    if (tx == 0) {
#pragma unroll
        for (int i = 0; i < 8; i++)
            bs[((size_t)(b*NHASH + h))*LTOK + s_tq[r0+i]] = m[i] + __logf(s[i]);
    }
}

// ---------------- combine hash rounds + residual ---------------------------
__global__ void combine_kernel(const float* __restrict__ ret, const float* __restrict__ bs,
                               const float* __restrict__ resid, float* __restrict__ out) {
    int b = blockIdx.y, t0 = blockIdx.x*32;
    __shared__ float s_p[NHASH][32];
    __shared__ float s_tile[64][33];
    int tid = threadIdx.x;
    if (tid < 32) {
        int t = t0 + tid;
        float v0 = bs[((size_t)(b*NHASH+0))*LTOK + t];
        float v1 = bs[((size_t)(b*NHASH+1))*LTOK + t];
        float v2 = bs[((size_t)(b*NHASH+2))*LTOK + t];
        float v3 = bs[((size_t)(b*NHASH+3))*LTOK + t];
        float mm = fmaxf(fmaxf(v0,v1), fmaxf(v2,v3));
        float p0 = __expf(v0-mm), p1 = __expf(v1-mm), p2 = __expf(v2-mm), p3 = __expf(v3-mm);
        float inv = 1.f/(p0+p1+p2+p3);
        s_p[0][tid] = p0*inv; s_p[1][tid] = p1*inv; s_p[2][tid] = p2*inv; s_p[3][tid] = p3*inv;
    }
    __syncthreads();
    for (int e = tid; e < 2048; e += 256) {
        int c = e & 63, tl = e >> 6;
        int t = t0 + tl;
        float a = 0.f;
#pragma unroll
        for (int h = 0; h < NHASH; h++)
            a = fmaf(s_p[h][tl], ret[(((size_t)(b*NHASH + h))*LTOK + t)*COUT + c], a);
        s_tile[c][tl] = a;
    }
    __syncthreads();
    for (int e = tid; e < 2048; e += 256) {
        int tl = e & 31, c = e >> 5;
        size_t idx = ((size_t)(b*COUT + c))*LTOK + t0 + tl;
        out[idx] = s_tile[c][tl] + resid[idx];
    }
}

// ---------------- launch -----------------------------------------------------
extern "C" void kernel_launch(void* const* d_in, const int* in_sizes, int n_in,
                              void* d_out, int out_size) {
    const float* x   = (const float*)d_in[0];
    const float* w1  = (const float*)d_in[1];
    const float* b1  = (const float*)d_in[2];
    const float* w2  = (const float*)d_in[3];
    const float* b2  = (const float*)d_in[4];
    const float* wm  = (const float*)d_in[5];
    const float* bm  = (const float*)d_in[6];
    const float* wa  = (const float*)d_in[7];
    const float* ba  = (const float*)d_in[8];
    const float* rot = (const float*)d_in[9];
    float* out = (float*)d_out;

    float *up, *c1, *c2, *xe, *ye, *ret, *bsp;
    int *codes, *hist, *pref, *sorted;
    cudaGetSymbolAddress((void**)&up,    g_up);
    cudaGetSymbolAddress((void**)&c1,    g_c1);
    cudaGetSymbolAddress((void**)&c2,    g_c2);
    cudaGetSymbolAddress((void**)&xe,    g_xe);
    cudaGetSymbolAddress((void**)&ye,    g_ye);
    cudaGetSymbolAddress((void**)&ret,   g_ret);
    cudaGetSymbolAddress((void**)&bsp,   g_bs);
    cudaGetSymbolAddress((void**)&codes, g_codes);
    cudaGetSymbolAddress((void**)&hist,  g_hist);
    cudaGetSymbolAddress((void**)&pref,  g_pref);
    cudaGetSymbolAddress((void**)&sorted,g_sorted);

    cudaFuncSetAttribute(attn_kernel, cudaFuncAttributeMaxDynamicSharedMemorySize, ATTN_SMEM);

    // 1. bicubic upsample
    upsample_kernel<<<(NB*CIN*HH*WW + 255)/256, 256>>>(x, up);
    // 2-3. conv3x3 + relu x2 (register-prefetch double-buffered)
    conv3x3_kernel<<<dim3(3,3,NB*8), 256>>>(up, w1, b1, c1, CIN,  COUT, 1, 0);
    conv3x3_kernel<<<dim3(3,3,NB*8), 256>>>(c1, w2, b2, c2, COUT, COUT, 1, 0);
    // 4. match conv -> x_embed token-major
    conv3x3_kernel<<<dim3(3,3,NB*4), 256>>>(c2, wm, bm, xe, COUT, CM, 0, 1);
    // 5. assembly 1x1 -> y_embed token-major
    conv1x1_kernel<<<dim3(LTOK/64, NB), 256>>>(c2, wa, ba, ye);
    // 6. LSH codes (packed)
    hash_kernel<<<NB*LTOK/128, 128>>>(xe, rot, codes);
    // 7. stable counting sort
    zero_hist_kernel<<<NB, 256>>>(hist);
    hist_kernel<<<(NB*LSORT + 255)/256, 256>>>(codes, hist);
    prefix_kernel<<<1, 32>>>(hist, pref);
    scatter_kernel<<<NB*TOTCODE/8, 256>>>(codes, pref, sorted);
    // 8. chunked attention (288 threads: 18 row-groups x 16 key-threads)
    attn_kernel<<<NB*NHASH*KCHUNKS, 288, ATTN_SMEM>>>(xe, ye, sorted, ret, bsp);
    // 9. combine hash rounds + residual
    combine_kernel<<<dim3(LTOK/32, NB), 256>>>(ret, bsp, c2, out);
}

// round 15
// speedup vs baseline: 1.0770x; 1.0061x over previous
#include <cuda_runtime.h>
#include <cuda_bf16.h>
#include <math.h>

// Problem constants
#define NB    4
#define CIN   64
#define HIN   48
#define WIN   48
#define COUT  64
#define CM    32
#define HH    96
#define WW    96
#define LTOK  (HH*WW)     // 9216
#define NHASH 4
#define BUCK  64
#define CHUNK 144
#define KCHUNKS (LTOK/CHUNK)   // 64
#define TOTCODE 256
#define LSORT (NHASH*LTOK)     // 36864
#define FULLMASK 0xffffffffu

typedef unsigned long long ull;

// ---------------- f32x2 packed-math helpers (exact fp32, 2x throughput) ------
__device__ __forceinline__ ull pk2(float lo, float hi) {
    ull r; asm("mov.b64 %0, {%1, %2};" : "=l"(r) : "f"(lo), "f"(hi)); return r;
}
__device__ __forceinline__ void upk2(ull v, float& lo, float& hi) {
    asm("mov.b64 {%0, %1}, %2;" : "=f"(lo), "=f"(hi) : "l"(v));
}
__device__ __forceinline__ ull ffma2(ull a, ull b, ull c) {
    ull d; asm("fma.rn.f32x2 %0, %1, %2, %3;" : "=l"(d) : "l"(a), "l"(b), "l"(c)); return d;
}

// ---------------- device scratch ----------------
__device__ float g_up [NB*CIN*HH*WW];
__device__ float g_c1 [NB*COUT*HH*WW];
__device__ float g_c2 [NB*COUT*HH*WW];
__device__ float g_xe [NB*LTOK*CM];
__device__ float g_ye [NB*LTOK*COUT];
__device__ int   g_codes[NB*NHASH*LTOK];
__device__ int   g_hist [NB*TOTCODE];
__device__ int   g_pref [NB*TOTCODE];
__device__ int   g_sorted[NB*LSORT];
__device__ float g_ret [NB*NHASH*LTOK*COUT];
__device__ float g_bs  [NB*NHASH*LTOK];

// ---------------- bicubic upsample ----------------
__device__ __forceinline__ float keysk(float x) {
    x = fabsf(x);
    if (x <= 1.f) return (1.5f*x - 2.5f)*x*x + 1.f;
    if (x <  2.f) return ((-0.5f*x + 2.5f)*x - 4.f)*x + 2.f;
    return 0.f;
}

__global__ void upsample_kernel(const float* __restrict__ in, float* __restrict__ out) {
    int g = blockIdx.x*256 + threadIdx.x;
    if (g >= NB*CIN*HH*WW) return;
    int ox = g % WW, oy = (g/WW) % HH, bc = g/(HH*WW);
    float sy = 0.5f*oy - 0.25f;
    float sx = 0.5f*ox - 0.25f;
    int iy0 = (int)floorf(sy) - 1;
    int ix0 = (int)floorf(sx) - 1;
    float wy[4], wx[4]; int iy[4], ix[4];
    float sumy = 0.f, sumx = 0.f;
#pragma unroll
    for (int j = 0; j < 4; j++) {
        int y = iy0 + j, x = ix0 + j;
        float wyv = (y >= 0 && y < HIN) ? keysk(sy - (float)y) : 0.f;
        float wxv = (x >= 0 && x < WIN) ? keysk(sx - (float)x) : 0.f;
        iy[j] = min(max(y,0), HIN-1); ix[j] = min(max(x,0), WIN-1);
        wy[j] = wyv; wx[j] = wxv; sumy += wyv; sumx += wxv;
    }
    float inv = 1.f/(sumy*sumx);
    const float* inp = in + (size_t)bc*HIN*WIN;
    float acc = 0.f;
#pragma unroll
    for (int jy = 0; jy < 4; jy++) {
        float row = 0.f;
#pragma unroll
        for (int jx = 0; jx < 4; jx++) row += wx[jx]*inp[iy[jy]*WIN + ix[jx]];
        acc += wy[jy]*row;
    }
    out[g] = acc*inv;
}

// -- 3x3 conv: 32x32 tile, 2x2 px/thread, 8 couts/block, half-stage prefetch -
#define STG   (4*1156)      // floats per input stage (4 channels of 34x34)
#define WSTG  (4*8*9)       // weight floats per stage (288)

__global__ void __launch_bounds__(256, 2) conv3x3_kernel(
    const float* __restrict__ in, const float* __restrict__ w,
    const float* __restrict__ bias, float* __restrict__ out,
    int CIN_, int COUT_, int relu, int token_major) {
    const int CPB = 8;
    int groups = COUT_/CPB;
    int z  = blockIdx.z;
    int cg = z % groups;
    int b  = z / groups;
    int tid = threadIdx.x;
    int tx = tid & 15, ty = tid >> 4;
    int ox0 = blockIdx.x*32, oy0 = blockIdx.y*32;
    __shared__ float s_in[2][STG];
    __shared__ float s_w[2][WSTG];

    // channel-local load slots (5 per channel; slot 4 partial for tid<132)
    int offc[5];
#pragma unroll
    for (int j = 0; j < 5; j++) {
        int e = tid + j*256;
        bool slot = (j < 4) || (tid < 132);
        int ly = e/34, lx = e - ly*34;
        int iy = oy0-1+ly, ix = ox0-1+lx;
        bool ok = slot && iy >= 0 && iy < HH && ix >= 0 && ix < WW;
        offc[j] = ok ? (iy*WW + ix) : -1;
    }
    int wb0, wb1;
    {
        int e = tid;
        int ch = e/72, rem = e - ch*72, co = rem/9, kk = rem - co*9;
        wb0 = ((cg*CPB+co)*CIN_ + ch)*9 + kk;
        e = 256 + tid;
        ch = e/72; rem = e - ch*72; co = rem/9; kk = rem - co*9;
        wb1 = ((cg*CPB+co)*CIN_ + ch)*9 + kk;
    }
    const float* inb = in + (size_t)b*CIN_*HH*WW;

    float acc[CPB][4];
#pragma unroll
    for (int i = 0; i < CPB; i++)
#pragma unroll
        for (int p = 0; p < 4; p++) acc[i][p] = 0.f;

    // stage 0 load
    {
#pragma unroll
        for (int ch = 0; ch < 4; ch++) {
            const float* inps = inb + (size_t)ch*HH*WW;
#pragma unroll
            for (int j = 0; j < 5; j++) {
                if (j < 4 || tid < 132)
                    s_in[0][ch*1156 + tid + j*256] = (offc[j] >= 0) ? inps[offc[j]] : 0.f;
            }
        }
        s_w[0][tid] = w[wb0];
        if (tid < 32) s_w[0][256+tid] = w[wb1];
    }
    __syncthreads();

    // per-channel compute helper macro kept inline for ptxas scheduling
    for (int s = 0; s < CIN_; s += 4) {
        int cur = (s >> 2) & 1;
        bool more = (s + 4 < CIN_);
        float r[10]; float rw0 = 0.f, rw1 = 0.f;

        // half A prefetch: channels 0-1 of next stage + weights
        if (more) {
            const float* inps = inb + (size_t)(s+4)*HH*WW;
#pragma unroll
            for (int ch = 0; ch < 2; ch++)
#pragma unroll
                for (int j = 0; j < 5; j++)
                    r[ch*5+j] = (offc[j] >= 0 && (j < 4 || tid < 132))
                              ? inps[(size_t)ch*HH*WW + offc[j]] : 0.f;
            rw0 = w[wb0 + (s+4)*9];
            if (tid < 32) rw1 = w[wb1 + (s+4)*9];
        }
        // compute channels 0-1
#pragma unroll
        for (int ch = 0; ch < 2; ch++) {
            float win[4][4];
            const float* base = s_in[cur] + ch*1156 + (2*ty)*34 + 2*tx;
#pragma unroll
            for (int rr = 0; rr < 4; rr++) {
                float2 a = *(const float2*)(base + rr*34);
                float2 bq = *(const float2*)(base + rr*34 + 2);
                win[rr][0] = a.x; win[rr][1] = a.y; win[rr][2] = bq.x; win[rr][3] = bq.y;
            }
            const float* wp = s_w[cur] + ch*CPB*9;
#pragma unroll
            for (int co = 0; co < CPB; co++) {
                float wr[9];
#pragma unroll
                for (int kk = 0; kk < 9; kk++) wr[kk] = wp[co*9+kk];
#pragma unroll
                for (int rr = 0; rr < 2; rr++)
#pragma unroll
                    for (int c = 0; c < 2; c++) {
                        float a = acc[co][rr*2+c];
#pragma unroll
                        for (int ky = 0; ky < 3; ky++)
#pragma unroll
                            for (int kx = 0; kx < 3; kx++)
                                a = fmaf(win[rr+ky][c+kx], wr[ky*3+kx], a);
                        acc[co][rr*2+c] = a;
                    }
            }
        }
        // commit half A, prefetch half B (channels 2-3)
        if (more) {
            float* dst = s_in[cur^1];
#pragma unroll
            for (int ch = 0; ch < 2; ch++)
#pragma unroll
                for (int j = 0; j < 5; j++)
                    if (j < 4 || tid < 132) dst[ch*1156 + tid + j*256] = r[ch*5+j];
            const float* inps = inb + (size_t)(s+4)*HH*WW;
#pragma unroll
            for (int ch = 0; ch < 2; ch++)
#pragma unroll
                for (int j = 0; j < 5; j++)
                    r[ch*5+j] = (offc[j] >= 0 && (j < 4 || tid < 132))
                              ? inps[(size_t)(ch+2)*HH*WW + offc[j]] : 0.f;
        }
        // compute channels 2-3
#pragma unroll
        for (int ch = 2; ch < 4; ch++) {
            float win[4][4];
            const float* base = s_in[cur] + ch*1156 + (2*ty)*34 + 2*tx;
#pragma unroll
            for (int rr = 0; rr < 4; rr++) {
                float2 a = *(const float2*)(base + rr*34);
                float2 bq = *(const float2*)(base + rr*34 + 2);
                win[rr][0] = a.x; win[rr][1] = a.y; win[rr][2] = bq.x; win[rr][3] = bq.y;
            }
            const float* wp = s_w[cur] + ch*CPB*9;
#pragma unroll
            for (int co = 0; co < CPB; co++) {
                float wr[9];
#pragma unroll
                for (int kk = 0; kk < 9; kk++) wr[kk] = wp[co*9+kk];
#pragma unroll
                for (int rr = 0; rr < 2; rr++)
#pragma unroll
                    for (int c = 0; c < 2; c++) {
                        float a = acc[co][rr*2+c];
#pragma unroll
                        for (int ky = 0; ky < 3; ky++)
#pragma unroll
                            for (int kx = 0; kx < 3; kx++)
                                a = fmaf(win[rr+ky][c+kx], wr[ky*3+kx], a);
                        acc[co][rr*2+c] = a;
                    }
            }
        }
        // commit half B + weights
        if (more) {
            float* dst = s_in[cur^1];
#pragma unroll
            for (int ch = 0; ch < 2; ch++)
#pragma unroll
                for (int j = 0; j < 5; j++)
                    if (j < 4 || tid < 132) dst[(ch+2)*1156 + tid + j*256] = r[ch*5+j];
            s_w[cur^1][tid] = rw0;
            if (tid < 32) s_w[cur^1][256+tid] = rw1;
        }
        __syncthreads();
    }
#pragma unroll
    for (int co = 0; co < CPB; co++) {
        int cout = cg*CPB + co;
        float bv = bias[cout];
#pragma unroll
        for (int rr = 0; rr < 2; rr++) {
            float v0 = acc[co][rr*2+0] + bv;
            float v1 = acc[co][rr*2+1] + bv;
            if (relu) { v0 = fmaxf(v0, 0.f); v1 = fmaxf(v1, 0.f); }
            int row = oy0 + 2*ty + rr, col = ox0 + 2*tx;
            if (token_major) {
                out[((size_t)b*LTOK + row*WW + col    )*COUT_ + cout] = v0;
                out[((size_t)b*LTOK + row*WW + col + 1)*COUT_ + cout] = v1;
            } else {
                *(float2*)&out[((size_t)(b*COUT_+cout))*LTOK + row*WW + col] =
                    make_float2(v0, v1);
            }
        }
    }
}

// ---------------- 1x1 conv -> y_embed [b][t][64] --------------------------
__global__ void conv1x1_kernel(const float* __restrict__ in, const float* __restrict__ w,
                               const float* __restrict__ bias, float* __restrict__ out) {
    int b  = blockIdx.y;
    int t0 = blockIdx.x*64;
    __shared__ float s_x[64][65];
    __shared__ float s_w[64][65];
    int tid = threadIdx.x;
    for (int e = tid; e < 64*64; e += 256) {
        int ci = e >> 6, tt = e & 63;
        s_x[ci][tt] = in[((size_t)(b*COUT+ci))*LTOK + t0 + tt];
        int co = e & 63, ci2 = e >> 6;
        s_w[ci2][co] = w[co*64 + ci2];
    }
    __syncthreads();
    int co = tid & 63;
    int ts = tid >> 6;
    for (int tt = ts; tt < 64; tt += 4) {
        float a = bias[co];
#pragma unroll
        for (int ci = 0; ci < 64; ci++) a = fmaf(s_x[ci][tt], s_w[ci][co], a);
        out[((size_t)b*LTOK + t0 + tt)*COUT + co] = a;
    }
}

// ---------------- LSH hashing (f32x2 packed over bucket pairs) --------------
__global__ void hash_kernel(const float* __restrict__ xe, const float* __restrict__ rot,
                            int* __restrict__ codes) {
    __shared__ __align__(16) float s_rot[CM*NHASH*32];
    int tid = threadIdx.x;
    for (int e = tid; e < CM*NHASH*32; e += 128) s_rot[e] = rot[e];
    __syncthreads();
    int g = blockIdx.x*128 + tid;
    float xf[CM];
    const float* xp = xe + (size_t)g*CM;
#pragma unroll
    for (int f = 0; f < CM; f++) xf[f] = xp[f];
    int b = g / LTOK, t = g % LTOK;
    for (int h = 0; h < NHASH; h++) {
        ull acc2[16];
#pragma unroll
        for (int i = 0; i < 16; i++) acc2[i] = 0ull;
#pragma unroll 4
        for (int f = 0; f < CM; f++) {
            ull x2 = pk2(xf[f], xf[f]);
            const ull* rp = (const ull*)&s_rot[(f*NHASH + h)*32];
#pragma unroll
            for (int i = 0; i < 16; i++) acc2[i] = ffma2(x2, rp[i], acc2[i]);
        }
        float sv[32];
#pragma unroll
        for (int i = 0; i < 16; i++) upk2(acc2[i], sv[2*i], sv[2*i+1]);
        float bv = sv[0]; int bi = 0;
#pragma unroll
        for (int i = 1; i < 32; i++) if (sv[i] > bv) { bv = sv[i]; bi = i; }
#pragma unroll
        for (int i = 0; i < 32; i++) if (-sv[i] > bv) { bv = -sv[i]; bi = 32 + i; }
        codes[((size_t)(b*NHASH + h))*LTOK + t] = h*BUCK + bi;
    }
}

// ---------------- counting sort ----------------
__global__ void zero_hist_kernel(int* h) { h[blockIdx.x*256 + threadIdx.x] = 0; }

__global__ void hist_kernel(const int* __restrict__ codes, int* __restrict__ hist) {
    int g = blockIdx.x*256 + threadIdx.x;
    if (g < NB*LSORT) {
        int b = g / LSORT;
        atomicAdd(&hist[b*TOTCODE + codes[g]], 1);
    }
}

__global__ void prefix_kernel(const int* __restrict__ hist, int* __restrict__ pref) {
    int b = threadIdx.x;
    if (b < NB) {
        int s = 0;
        for (int c = 0; c < TOTCODE; c++) { pref[b*TOTCODE + c] = s; s += hist[b*TOTCODE + c]; }
    }
}

__global__ void scatter_kernel(const int* __restrict__ codes, const int* __restrict__ pref,
                               int* __restrict__ sorted_p) {
    int wid  = (blockIdx.x*blockDim.x + threadIdx.x) >> 5;
    int lane = threadIdx.x & 31;
    if (wid >= NB*TOTCODE) return;
    int b = wid >> 8, c = wid & 255;
    int h = c >> 6;
    int base = pref[b*TOTCODE + c];
    const int* cp = codes + ((size_t)(b*NHASH + h))*LTOK;
    int off = 0;
    for (int t0 = 0; t0 < LTOK; t0 += 32) {
        int t = t0 + lane;
        bool m = (cp[t] == c);
        unsigned mask = __ballot_sync(FULLMASK, m);
        if (m) {
            int pos = base + off + __popc(mask & ((1u << lane) - 1u));
            sorted_p[(size_t)b*LSORT + pos] = h*LTOK + t;
        }
        off += __popc(mask);
    }
}

// ---- chunked attention: known softmax max (m = |q|, self-match) -------------
// smem: KT[32*144] | QT[32*144] | Y[144*64] | P2[18][48][4]float2 | tq | nrm
#define ATTN_SMEM ((32*144*2 + 144*64)*4 + 18*48*4*8 + 144*4 + 144*4)

__device__ __forceinline__ float gsum16(float v) {
    v += __shfl_xor_sync(FULLMASK, v, 1);
    v += __shfl_xor_sync(FULLMASK, v, 2);
    v += __shfl_xor_sync(FULLMASK, v, 4);
    v += __shfl_xor_sync(FULLMASK, v, 8);
    return v;
}

__global__ void __launch_bounds__(288, 2) attn_kernel(
    const float* __restrict__ xe, const float* __restrict__ ye,
    const int* __restrict__ sorted_p, float* __restrict__ ret, float* __restrict__ bs) {
    extern __shared__ float sm[];
    float*  s_KT = sm;                   // [32][144] normalized keys
    float*  s_QT = s_KT + 32*144;        // [32][144]
    float*  s_Y  = s_QT + 32*144;        // [144][64]
    float2* s_P2 = (float2*)(s_Y + 144*64);   // [18][48][4] row-pair dups
    int*    s_tq = (int*)(s_P2 + 18*48*4);
    float*  s_m  = (float*)(s_tq + 144);      // |q| per row

    int blk = blockIdx.x;
    int k = blk & 63, h = (blk >> 6) & 3, b = blk >> 8;
    int tid = threadIdx.x;
    int tx = tid & 15, ty = tid >> 4;    // ty 0..17
    int r0 = ty*8, c0 = tx*4, jbase = tx*3;
    const int* spb = sorted_p + (size_t)b*LSORT + h*LTOK;

    if (tid < 144)
        s_tq[tid] = spb[k*CHUNK + tid] - h*LTOK;
    __syncthreads();
    for (int e = tid; e < 144*8; e += 288) {     // Q transposed, f-major
        int j = e >> 3, q = e & 7;
        float4 v = *(const float4*)(xe + ((size_t)b*LTOK + s_tq[j])*CM + q*4);
        s_QT[(q*4+0)*144 + j] = v.x; s_QT[(q*4+1)*144 + j] = v.y;
        s_QT[(q*4+2)*144 + j] = v.z; s_QT[(q*4+3)*144 + j] = v.w;
    }

    float m[8], s[8];
    ull o2[4][4];                         // o2[pair][c] = (row 2p, row 2p+1)
#pragma unroll
    for (int i = 0; i < 8; i++) s[i] = 0.f;
#pragma unroll
    for (int p = 0; p < 4; p++)
#pragma unroll
        for (int c = 0; c < 4; c++) o2[p][c] = 0ull;

#pragma unroll 1
    for (int cc = 0; cc < 3; cc++) {
        int kc = (cc == 0) ? k : (cc == 1 ? (k + KCHUNKS - 1) % KCHUNKS
                                          : (k + 1) % KCHUNKS);
        __syncthreads();
        if (tid < 144) {
            // one thread = one key column: load, normalize in regs, store transposed
            int tok = spb[kc*CHUNK + tid] - h*LTOK;
            const float* xp = xe + ((size_t)b*LTOK + tok)*CM;
            float v[32]; float ss = 0.f;
#pragma unroll
            for (int q = 0; q < 8; q++) {
                float4 t4 = *(const float4*)(xp + q*4);
                v[q*4+0] = t4.x; v[q*4+1] = t4.y; v[q*4+2] = t4.z; v[q*4+3] = t4.w;
            }
#pragma unroll
            for (int f = 0; f < 32; f++) ss = fmaf(v[f], v[f], ss);
            float nrm = sqrtf(ss);
            if (cc == 0) s_m[tid] = nrm;   // chunk-0 keys ARE the queries: m = |q|
            float inv = 1.f / fmaxf(nrm, 5e-5f);
#pragma unroll
            for (int f = 0; f < 32; f++) s_KT[f*144 + tid] = v[f]*inv;
        } else {
            // other 144 threads load Y concurrently
            for (int e = tid - 144; e < 144*16; e += 144) {
                int j = e >> 4, q = e & 15;
                int tok = spb[kc*CHUNK + j] - h*LTOK;
                float4 vv = *(const float4*)(ye + ((size_t)b*LTOK + tok)*COUT + q*4);
                *(float4*)(s_Y + j*64 + q*4) = vv;
            }
        }
        __syncthreads();
        if (cc == 0) {
#pragma unroll
            for (int i = 0; i < 8; i++) m[i] = s_m[r0 + i];
        }

#pragma unroll 1
        for (int w = 0; w < 3; w++) {               // 48-key windows
            int kw0 = w*48;
            // GEMM1: packed S(4 pairs x 3 keys)
            ull acc2[4][3];
#pragma unroll
            for (int p = 0; p < 4; p++)
#pragma unroll
                for (int j = 0; j < 3; j++) acc2[p][j] = 0ull;
#pragma unroll 2
            for (int f = 0; f < 32; f++) {
                ull qv[4];
#pragma unroll
                for (int p = 0; p < 4; p++)
                    qv[p] = *(const ull*)(s_QT + f*144 + r0 + 2*p);
#pragma unroll
                for (int j = 0; j < 3; j++) {
                    float kv = s_KT[f*144 + kw0 + jbase + j];
                    ull k2 = pk2(kv, kv);
#pragma unroll
                    for (int p = 0; p < 4; p++)
                        acc2[p][j] = ffma2(qv[p], k2, acc2[p][j]);
                }
            }
            // softmax with known max: p = exp(s - |q|); no reductions, no rescale
            float a[8][3];
#pragma unroll
            for (int p = 0; p < 4; p++)
#pragma unroll
                for (int j = 0; j < 3; j++) upk2(acc2[p][j], a[2*p][j], a[2*p+1][j]);
#pragma unroll
            for (int i = 0; i < 8; i++) {
#pragma unroll
                for (int j = 0; j < 3; j++) {
                    float pv = __expf(a[i][j] - m[i]);
                    a[i][j] = pv; s[i] += pv;
                }
            }
            __syncwarp();          // prior window's P reads complete
#pragma unroll
            for (int j = 0; j < 3; j++)
#pragma unroll
                for (int p = 0; p < 4; p++)
                    s_P2[(ty*48 + jbase + j)*4 + p] = make_float2(a[2*p][j], a[2*p+1][j]);
            __syncwarp();          // P visible to half-warp
            // GEMM2: O += P*Y (packed over row pairs)
#pragma unroll 2
            for (int key = 0; key < 48; key++) {
                float4 y = *(const float4*)(s_Y + (kw0 + key)*64 + c0);
                ull yd[4] = { pk2(y.x,y.x), pk2(y.y,y.y), pk2(y.z,y.z), pk2(y.w,y.w) };
                const ull* pp = (const ull*)&s_P2[(ty*48 + key)*4];
#pragma unroll
                for (int p = 0; p < 4; p++) {
                    ull pv = pp[p];
#pragma unroll
                    for (int c = 0; c < 4; c++)
                        o2[p][c] = ffma2(pv, yd[c], o2[p][c]);
                }
            }
        }
    }

    // epilogue: single cross-thread sum reduction per row
#pragma unroll
    for (int i = 0; i < 8; i++) s[i] = gsum16(s[i]);
#pragma unroll
    for (int p = 0; p < 4; p++) {
        float lo[4], hi[4];
#pragma unroll
        for (int c = 0; c < 4; c++) upk2(o2[p][c], lo[c], hi[c]);
        float inv0 = 1.f / s[2*p], inv1 = 1.f / s[2*p+1];
        *(float4*)(ret + (((size_t)(b*NHASH + h))*LTOK + s_tq[r0+2*p  ])*COUT + c0) =
            make_float4(lo[0]*inv0, lo[1]*inv0, lo[2]*inv0, lo[3]*inv0);
        *(float4*)(ret + (((size_t)(b*NHASH + h))*LTOK + s_tq[r0+2*p+1])*COUT + c0) =
            make_float4(hi[0]*inv1, hi[1]*inv1, hi[2]*inv1, hi[3]*inv1);
    }
    if (tx == 0) {
#pragma unroll
        for (int i = 0; i < 8; i++)
            bs[((size_t)(b*NHASH + h))*LTOK + s_tq[r0+i]] = m[i] + __logf(s[i]);
    }
}

// ---------------- combine hash rounds + residual ---------------------------
__global__ void combine_kernel(const float* __restrict__ ret, const float* __restrict__ bs,
                               const float* __restrict__ resid, float* __restrict__ out) {
    int b = blockIdx.y, t0 = blockIdx.x*32;
    __shared__ float s_p[NHASH][32];
    __shared__ float s_tile[64][33];
    int tid = threadIdx.x;
    if (tid < 32) {
        int t = t0 + tid;
        float v0 = bs[((size_t)(b*NHASH+0))*LTOK + t];
        float v1 = bs[((size_t)(b*NHASH+1))*LTOK + t];
        float v2 = bs[((size_t)(b*NHASH+2))*LTOK + t];
        float v3 = bs[((size_t)(b*NHASH+3))*LTOK + t];
        float mm = fmaxf(fmaxf(v0,v1), fmaxf(v2,v3));
        float p0 = __expf(v0-mm), p1 = __expf(v1-mm), p2 = __expf(v2-mm), p3 = __expf(v3-mm);
        float inv = 1.f/(p0+p1+p2+p3);
        s_p[0][tid] = p0*inv; s_p[1][tid] = p1*inv; s_p[2][tid] = p2*inv; s_p[3][tid] = p3*inv;
    }
    __syncthreads();
    for (int e = tid; e < 2048; e += 256) {
        int c = e & 63, tl = e >> 6;
        int t = t0 + tl;
        float a = 0.f;
#pragma unroll
        for (int h = 0; h < NHASH; h++)
            a = fmaf(s_p[h][tl], ret[(((size_t)(b*NHASH + h))*LTOK + t)*COUT + c], a);
        s_tile[c][tl] = a;
    }
    __syncthreads();
    for (int e = tid; e < 2048; e += 256) {
        int tl = e & 31, c = e >> 5;
        size_t idx = ((size_t)(b*COUT + c))*LTOK + t0 + tl;
        out[idx] = s_tile[c][tl] + resid[idx];
    }
}

// ---------------- launch -----------------------------------------------------
extern "C" void kernel_launch(void* const* d_in, const int* in_sizes, int n_in,
                              void* d_out, int out_size) {
    const float* x   = (const float*)d_in[0];
    const float* w1  = (const float*)d_in[1];
    const float* b1  = (const float*)d_in[2];
    const float* w2  = (const float*)d_in[3];
    const float* b2  = (const float*)d_in[4];
    const float* wm  = (const float*)d_in[5];
    const float* bm  = (const float*)d_in[6];
    const float* wa  = (const float*)d_in[7];
    const float* ba  = (const float*)d_in[8];
    const float* rot = (const float*)d_in[9];
    float* out = (float*)d_out;

    float *up, *c1, *c2, *xe, *ye, *ret, *bsp;
    int *codes, *hist, *pref, *sorted;
    cudaGetSymbolAddress((void**)&up,    g_up);
    cudaGetSymbolAddress((void**)&c1,    g_c1);
    cudaGetSymbolAddress((void**)&c2,    g_c2);
    cudaGetSymbolAddress((void**)&xe,    g_xe);
    cudaGetSymbolAddress((void**)&ye,    g_ye);
    cudaGetSymbolAddress((void**)&ret,   g_ret);
    cudaGetSymbolAddress((void**)&bsp,   g_bs);
    cudaGetSymbolAddress((void**)&codes, g_codes);
    cudaGetSymbolAddress((void**)&hist,  g_hist);
    cudaGetSymbolAddress((void**)&pref,  g_pref);
    cudaGetSymbolAddress((void**)&sorted,g_sorted);

    cudaFuncSetAttribute(attn_kernel, cudaFuncAttributeMaxDynamicSharedMemorySize, ATTN_SMEM);

    // 1. bicubic upsample
    upsample_kernel<<<(NB*CIN*HH*WW + 255)/256, 256>>>(x, up);
    // 2-3. conv3x3 + relu x2 (half-stage register prefetch, 2 blocks/SM)
    conv3x3_kernel<<<dim3(3,3,NB*8), 256>>>(up, w1, b1, c1, CIN,  COUT, 1, 0);
    conv3x3_kernel<<<dim3(3,3,NB*8), 256>>>(c1, w2, b2, c2, COUT, COUT, 1, 0);
    // 4. match conv -> x_embed token-major
    conv3x3_kernel<<<dim3(3,3,NB*4), 256>>>(c2, wm, bm, xe, COUT, CM, 0, 1);
    // 5. assembly 1x1 -> y_embed token-major
    conv1x1_kernel<<<dim3(LTOK/64, NB), 256>>>(c2, wa, ba, ye);
    // 6. LSH codes (packed)
    hash_kernel<<<NB*LTOK/128, 128>>>(xe, rot, codes);
    // 7. stable counting sort
    zero_hist_kernel<<<NB, 256>>>(hist);
    hist_kernel<<<(NB*LSORT + 255)/256, 256>>>(codes, hist);
    prefix_kernel<<<1, 32>>>(hist, pref);
    scatter_kernel<<<NB*TOTCODE/8, 256>>>(codes, pref, sorted);
    // 8. chunked attention (288 threads: 18 row-groups x 16 key-threads)
    attn_kernel<<<NB*NHASH*KCHUNKS, 288, ATTN_SMEM>>>(xe, ye, sorted, ret, bsp);
    // 9. combine hash rounds + residual
    combine_kernel<<<dim3(LTOK/32, NB), 256>>>(ret, bsp, c2, out);
}

// round 16
// speedup vs baseline: 1.0835x; 1.0060x over previous
#include <cuda_runtime.h>
#include <cuda_bf16.h>
#include <math.h>

// Problem constants
#define NB    4
#define CIN   64
#define HIN   48
#define WIN   48
#define COUT  64
#define CM    32
#define HH    96
#define WW    96
#define LTOK  (HH*WW)     // 9216
#define NHASH 4
#define BUCK  64
#define CHUNK 144
#define KCHUNKS (LTOK/CHUNK)   // 64
#define TOTCODE 256
#define LSORT (NHASH*LTOK)     // 36864
#define FULLMASK 0xffffffffu

typedef unsigned long long ull;

// ---------------- f32x2 packed-math helpers (exact fp32, 2x throughput) ------
__device__ __forceinline__ ull pk2(float lo, float hi) {
    ull r; asm("mov.b64 %0, {%1, %2};" : "=l"(r) : "f"(lo), "f"(hi)); return r;
}
__device__ __forceinline__ void upk2(ull v, float& lo, float& hi) {
    asm("mov.b64 {%0, %1}, %2;" : "=f"(lo), "=f"(hi) : "l"(v));
}
__device__ __forceinline__ ull ffma2(ull a, ull b, ull c) {
    ull d; asm("fma.rn.f32x2 %0, %1, %2, %3;" : "=l"(d) : "l"(a), "l"(b), "l"(c)); return d;
}

// ---------------- device scratch ----------------
__device__ float g_up [NB*CIN*HH*WW];
__device__ float g_c1 [NB*COUT*HH*WW];
__device__ float g_c2 [NB*COUT*HH*WW];
__device__ float g_xe [NB*LTOK*CM];
__device__ float g_xn [NB*LTOK*CM];     // normalized x_embed (token-major)
__device__ float g_nrm[NB*LTOK];        // |x_embed| per token
__device__ float g_ye [NB*LTOK*COUT];
__device__ int   g_codes[NB*NHASH*LTOK];
__device__ int   g_hist [NB*TOTCODE];
__device__ int   g_pref [NB*TOTCODE];
__device__ int   g_sorted[NB*LSORT];
__device__ float g_ret [NB*NHASH*LTOK*COUT];
__device__ float g_bs  [NB*NHASH*LTOK];

// ---------------- bicubic upsample ----------------
__device__ __forceinline__ float keysk(float x) {
    x = fabsf(x);
    if (x <= 1.f) return (1.5f*x - 2.5f)*x*x + 1.f;
    if (x <  2.f) return ((-0.5f*x + 2.5f)*x - 4.f)*x + 2.f;
    return 0.f;
}

__global__ void upsample_kernel(const float* __restrict__ in, float* __restrict__ out) {
    int g = blockIdx.x*256 + threadIdx.x;
    if (g >= NB*CIN*HH*WW) return;
    int ox = g % WW, oy = (g/WW) % HH, bc = g/(HH*WW);
    float sy = 0.5f*oy - 0.25f;
    float sx = 0.5f*ox - 0.25f;
    int iy0 = (int)floorf(sy) - 1;
    int ix0 = (int)floorf(sx) - 1;
    float wy[4], wx[4]; int iy[4], ix[4];
    float sumy = 0.f, sumx = 0.f;
#pragma unroll
    for (int j = 0; j < 4; j++) {
        int y = iy0 + j, x = ix0 + j;
        float wyv = (y >= 0 && y < HIN) ? keysk(sy - (float)y) : 0.f;
        float wxv = (x >= 0 && x < WIN) ? keysk(sx - (float)x) : 0.f;
        iy[j] = min(max(y,0), HIN-1); ix[j] = min(max(x,0), WIN-1);
        wy[j] = wyv; wx[j] = wxv; sumy += wyv; sumx += wxv;
    }
    float inv = 1.f/(sumy*sumx);
    const float* inp = in + (size_t)bc*HIN*WIN;
    float acc = 0.f;
#pragma unroll
    for (int jy = 0; jy < 4; jy++) {
        float row = 0.f;
#pragma unroll
        for (int jx = 0; jx < 4; jx++) row += wx[jx]*inp[iy[jy]*WIN + ix[jx]];
        acc += wy[jy]*row;
    }
    out[g] = acc*inv;
}

// -- 3x3 conv: 32x32 tile, 2x2 px/thread, 8 couts/block, half-stage prefetch -
#define STG   (4*1156)
#define WSTG  (4*8*9)

__global__ void __launch_bounds__(256, 2) conv3x3_kernel(
    const float* __restrict__ in, const float* __restrict__ w,
    const float* __restrict__ bias, float* __restrict__ out,
    int CIN_, int COUT_, int relu, int token_major) {
    const int CPB = 8;
    int groups = COUT_/CPB;
    int z  = blockIdx.z;
    int cg = z % groups;
    int b  = z / groups;
    int tid = threadIdx.x;
    int tx = tid & 15, ty = tid >> 4;
    int ox0 = blockIdx.x*32, oy0 = blockIdx.y*32;
    __shared__ float s_in[2][STG];
    __shared__ float s_w[2][WSTG];

    int offc[5];
#pragma unroll
    for (int j = 0; j < 5; j++) {
        int e = tid + j*256;
        bool slot = (j < 4) || (tid < 132);
        int ly = e/34, lx = e - ly*34;
        int iy = oy0-1+ly, ix = ox0-1+lx;
        bool ok = slot && iy >= 0 && iy < HH && ix >= 0 && ix < WW;
        offc[j] = ok ? (iy*WW + ix) : -1;
    }
    int wb0, wb1;
    {
        int e = tid;
        int ch = e/72, rem = e - ch*72, co = rem/9, kk = rem - co*9;
        wb0 = ((cg*CPB+co)*CIN_ + ch)*9 + kk;
        e = 256 + tid;
        ch = e/72; rem = e - ch*72; co = rem/9; kk = rem - co*9;
        wb1 = ((cg*CPB+co)*CIN_ + ch)*9 + kk;
    }
    const float* inb = in + (size_t)b*CIN_*HH*WW;

    float acc[CPB][4];
#pragma unroll
    for (int i = 0; i < CPB; i++)
#pragma unroll
        for (int p = 0; p < 4; p++) acc[i][p] = 0.f;

    {
#pragma unroll
        for (int ch = 0; ch < 4; ch++) {
            const float* inps = inb + (size_t)ch*HH*WW;
#pragma unroll
            for (int j = 0; j < 5; j++) {
                if (j < 4 || tid < 132)
                    s_in[0][ch*1156 + tid + j*256] = (offc[j] >= 0) ? inps[offc[j]] : 0.f;
            }
        }
        s_w[0][tid] = w[wb0];
        if (tid < 32) s_w[0][256+tid] = w[wb1];
    }
    __syncthreads();

    for (int s = 0; s < CIN_; s += 4) {
        int cur = (s >> 2) & 1;
        bool more = (s + 4 < CIN_);
        float r[10]; float rw0 = 0.f, rw1 = 0.f;

        if (more) {
            const float* inps = inb + (size_t)(s+4)*HH*WW;
#pragma unroll
            for (int ch = 0; ch < 2; ch++)
#pragma unroll
                for (int j = 0; j < 5; j++)
                    r[ch*5+j] = (offc[j] >= 0 && (j < 4 || tid < 132))
                              ? inps[(size_t)ch*HH*WW + offc[j]] : 0.f;
            rw0 = w[wb0 + (s+4)*9];
            if (tid < 32) rw1 = w[wb1 + (s+4)*9];
        }
#pragma unroll
        for (int ch = 0; ch < 2; ch++) {
            float win[4][4];
            const float* base = s_in[cur] + ch*1156 + (2*ty)*34 + 2*tx;
#pragma unroll
            for (int rr = 0; rr < 4; rr++) {
                float2 a = *(const float2*)(base + rr*34);
                float2 bq = *(const float2*)(base + rr*34 + 2);
                win[rr][0] = a.x; win[rr][1] = a.y; win[rr][2] = bq.x; win[rr][3] = bq.y;
            }
            const float* wp = s_w[cur] + ch*CPB*9;
#pragma unroll
            for (int co = 0; co < CPB; co++) {
                float wr[9];
#pragma unroll
                for (int kk = 0; kk < 9; kk++) wr[kk] = wp[co*9+kk];
#pragma unroll
                for (int rr = 0; rr < 2; rr++)
#pragma unroll
                    for (int c = 0; c < 2; c++) {
                        float a = acc[co][rr*2+c];
#pragma unroll
                        for (int ky = 0; ky < 3; ky++)
#pragma unroll
                            for (int kx = 0; kx < 3; kx++)
                                a = fmaf(win[rr+ky][c+kx], wr[ky*3+kx], a);
                        acc[co][rr*2+c] = a;
                    }
            }
        }
        if (more) {
            float* dst = s_in[cur^1];
#pragma unroll
            for (int ch = 0; ch < 2; ch++)
#pragma unroll
                for (int j = 0; j < 5; j++)
                    if (j < 4 || tid < 132) dst[ch*1156 + tid + j*256] = r[ch*5+j];
            const float* inps = inb + (size_t)(s+4)*HH*WW;
#pragma unroll
            for (int ch = 0; ch < 2; ch++)
#pragma unroll
                for (int j = 0; j < 5; j++)
                    r[ch*5+j] = (offc[j] >= 0 && (j < 4 || tid < 132))
                              ? inps[(size_t)(ch+2)*HH*WW + offc[j]] : 0.f;
        }
#pragma unroll
        for (int ch = 2; ch < 4; ch++) {
            float win[4][4];
            const float* base = s_in[cur] + ch*1156 + (2*ty)*34 + 2*tx;
#pragma unroll
            for (int rr = 0; rr < 4; rr++) {
                float2 a = *(const float2*)(base + rr*34);
                float2 bq = *(const float2*)(base + rr*34 + 2);
                win[rr][0] = a.x; win[rr][1] = a.y; win[rr][2] = bq.x; win[rr][3] = bq.y;
            }
            const float* wp = s_w[cur] + ch*CPB*9;
#pragma unroll
            for (int co = 0; co < CPB; co++) {
                float wr[9];
#pragma unroll
                for (int kk = 0; kk < 9; kk++) wr[kk] = wp[co*9+kk];
#pragma unroll
                for (int rr = 0; rr < 2; rr++)
#pragma unroll
                    for (int c = 0; c < 2; c++) {
                        float a = acc[co][rr*2+c];
#pragma unroll
                        for (int ky = 0; ky < 3; ky++)
#pragma unroll
                            for (int kx = 0; kx < 3; kx++)
                                a = fmaf(win[rr+ky][c+kx], wr[ky*3+kx], a);
                        acc[co][rr*2+c] = a;
                    }
            }
        }
        if (more) {
            float* dst = s_in[cur^1];
#pragma unroll
            for (int ch = 0; ch < 2; ch++)
#pragma unroll
                for (int j = 0; j < 5; j++)
                    if (j < 4 || tid < 132) dst[(ch+2)*1156 + tid + j*256] = r[ch*5+j];
            s_w[cur^1][tid] = rw0;
            if (tid < 32) s_w[cur^1][256+tid] = rw1;
        }
        __syncthreads();
    }
#pragma unroll
    for (int co = 0; co < CPB; co++) {
        int cout = cg*CPB + co;
        float bv = bias[cout];
#pragma unroll
        for (int rr = 0; rr < 2; rr++) {
            float v0 = acc[co][rr*2+0] + bv;
            float v1 = acc[co][rr*2+1] + bv;
            if (relu) { v0 = fmaxf(v0, 0.f); v1 = fmaxf(v1, 0.f); }
            int row = oy0 + 2*ty + rr, col = ox0 + 2*tx;
            if (token_major) {
                out[((size_t)b*LTOK + row*WW + col    )*COUT_ + cout] = v0;
                out[((size_t)b*LTOK + row*WW + col + 1)*COUT_ + cout] = v1;
            } else {
                *(float2*)&out[((size_t)(b*COUT_+cout))*LTOK + row*WW + col] =
                    make_float2(v0, v1);
            }
        }
    }
}

// ---------------- 1x1 conv -> y_embed [b][t][64] --------------------------
__global__ void conv1x1_kernel(const float* __restrict__ in, const float* __restrict__ w,
                               const float* __restrict__ bias, float* __restrict__ out) {
    int b  = blockIdx.y;
    int t0 = blockIdx.x*64;
    __shared__ float s_x[64][65];
    __shared__ float s_w[64][65];
    int tid = threadIdx.x;
    for (int e = tid; e < 64*64; e += 256) {
        int ci = e >> 6, tt = e & 63;
        s_x[ci][tt] = in[((size_t)(b*COUT+ci))*LTOK + t0 + tt];
        int co = e & 63, ci2 = e >> 6;
        s_w[ci2][co] = w[co*64 + ci2];
    }
    __syncthreads();
    int co = tid & 63;
    int ts = tid >> 6;
    for (int tt = ts; tt < 64; tt += 4) {
        float a = bias[co];
#pragma unroll
        for (int ci = 0; ci < 64; ci++) a = fmaf(s_x[ci][tt], s_w[ci][co], a);
        out[((size_t)b*LTOK + t0 + tt)*COUT + co] = a;
    }
}

// ------ LSH hashing (f32x2) + emit normalized x_embed and norms -------------
__global__ void hash_kernel(const float* __restrict__ xe, const float* __restrict__ rot,
                            int* __restrict__ codes,
                            float* __restrict__ xn, float* __restrict__ nrm_out) {
    __shared__ __align__(16) float s_rot[CM*NHASH*32];
    int tid = threadIdx.x;
    for (int e = tid; e < CM*NHASH*32; e += 128) s_rot[e] = rot[e];
    __syncthreads();
    int g = blockIdx.x*128 + tid;
    float xf[CM];
    const float* xp = xe + (size_t)g*CM;
#pragma unroll
    for (int f = 0; f < CM; f++) xf[f] = xp[f];
    // emit normalized copy + norm
    {
        float ss = 0.f;
#pragma unroll
        for (int f = 0; f < CM; f++) ss = fmaf(xf[f], xf[f], ss);
        float nrm = sqrtf(ss);
        nrm_out[g] = nrm;
        float inv = 1.f / fmaxf(nrm, 5e-5f);
        float* op = xn + (size_t)g*CM;
#pragma unroll
        for (int q = 0; q < 8; q++)
            *(float4*)(op + q*4) = make_float4(xf[q*4+0]*inv, xf[q*4+1]*inv,
                                               xf[q*4+2]*inv, xf[q*4+3]*inv);
    }
    int b = g / LTOK, t = g % LTOK;
    for (int h = 0; h < NHASH; h++) {
        ull acc2[16];
#pragma unroll
        for (int i = 0; i < 16; i++) acc2[i] = 0ull;
#pragma unroll 4
        for (int f = 0; f < CM; f++) {
            ull x2 = pk2(xf[f], xf[f]);
            const ull* rp = (const ull*)&s_rot[(f*NHASH + h)*32];
#pragma unroll
            for (int i = 0; i < 16; i++) acc2[i] = ffma2(x2, rp[i], acc2[i]);
        }
        float sv[32];
#pragma unroll
        for (int i = 0; i < 16; i++) upk2(acc2[i], sv[2*i], sv[2*i+1]);
        float bv = sv[0]; int bi = 0;
#pragma unroll
        for (int i = 1; i < 32; i++) if (sv[i] > bv) { bv = sv[i]; bi = i; }
#pragma unroll
        for (int i = 0; i < 32; i++) if (-sv[i] > bv) { bv = -sv[i]; bi = 32 + i; }
        codes[((size_t)(b*NHASH + h))*LTOK + t] = h*BUCK + bi;
    }
}

// ---------------- counting sort ----------------
__global__ void zero_hist_kernel(int* h) { h[blockIdx.x*256 + threadIdx.x] = 0; }

__global__ void hist_kernel(const int* __restrict__ codes, int* __restrict__ hist) {
    int g = blockIdx.x*256 + threadIdx.x;
    if (g < NB*LSORT) {
        int b = g / LSORT;
        atomicAdd(&hist[b*TOTCODE + codes[g]], 1);
    }
}

__global__ void prefix_kernel(const int* __restrict__ hist, int* __restrict__ pref) {
    int b = threadIdx.x;
    if (b < NB) {
        int s = 0;
        for (int c = 0; c < TOTCODE; c++) { pref[b*TOTCODE + c] = s; s += hist[b*TOTCODE + c]; }
    }
}

__global__ void scatter_kernel(const int* __restrict__ codes, const int* __restrict__ pref,
                               int* __restrict__ sorted_p) {
    int wid  = (blockIdx.x*blockDim.x + threadIdx.x) >> 5;
    int lane = threadIdx.x & 31;
    if (wid >= NB*TOTCODE) return;
    int b = wid >> 8, c = wid & 255;
    int h = c >> 6;
    int base = pref[b*TOTCODE + c];
    const int* cp = codes + ((size_t)(b*NHASH + h))*LTOK;
    int off = 0;
    for (int t0 = 0; t0 < LTOK; t0 += 32) {
        int t = t0 + lane;
        bool m = (cp[t] == c);
        unsigned mask = __ballot_sync(FULLMASK, m);
        if (m) {
            int pos = base + off + __popc(mask & ((1u << lane) - 1u));
            sorted_p[(size_t)b*LSORT + pos] = h*LTOK + t;
        }
        off += __popc(mask);
    }
}

// ---- chunked attention: prenormalized keys/queries, m = |q| known ----------
// score p = exp(|q|*(q_hat . k_hat - 1))
// smem: KT[32*144] | QT[32*144] | Y[144*64] | P2[18][48][4]float2 | tq | nrm
#define ATTN_SMEM ((32*144*2 + 144*64)*4 + 18*48*4*8 + 144*4 + 144*4)

__device__ __forceinline__ float gsum16(float v) {
    v += __shfl_xor_sync(FULLMASK, v, 1);
    v += __shfl_xor_sync(FULLMASK, v, 2);
    v += __shfl_xor_sync(FULLMASK, v, 4);
    v += __shfl_xor_sync(FULLMASK, v, 8);
    return v;
}

__global__ void __launch_bounds__(288, 2) attn_kernel(
    const float* __restrict__ xn, const float* __restrict__ nrm,
    const float* __restrict__ ye,
    const int* __restrict__ sorted_p, float* __restrict__ ret, float* __restrict__ bs) {
    extern __shared__ float sm[];
    float*  s_KT = sm;                   // [32][144] normalized keys
    float*  s_QT = s_KT + 32*144;        // [32][144] normalized queries
    float*  s_Y  = s_QT + 32*144;        // [144][64]
    float2* s_P2 = (float2*)(s_Y + 144*64);   // [18][48][4] row-pair dups
    int*    s_tq = (int*)(s_P2 + 18*48*4);
    float*  s_m  = (float*)(s_tq + 144);      // |q| per row

    int blk = blockIdx.x;
    int k = blk & 63, h = (blk >> 6) & 3, b = blk >> 8;
    int tid = threadIdx.x;
    int tx = tid & 15, ty = tid >> 4;    // ty 0..17
    int r0 = ty*8, c0 = tx*4, jbase = tx*3;
    const int* spb = sorted_p + (size_t)b*LSORT + h*LTOK;

    if (tid < 144)
        s_tq[tid] = spb[k*CHUNK + tid] - h*LTOK;
    __syncthreads();
    if (tid < 144)
        s_m[tid] = nrm[(size_t)b*LTOK + s_tq[tid]];
    for (int e = tid; e < 144*8; e += 288) {     // normalized Q transposed
        int j = e >> 3, q = e & 7;
        float4 v = *(const float4*)(xn + ((size_t)b*LTOK + s_tq[j])*CM + q*4);
        s_QT[(q*4+0)*144 + j] = v.x; s_QT[(q*4+1)*144 + j] = v.y;
        s_QT[(q*4+2)*144 + j] = v.z; s_QT[(q*4+3)*144 + j] = v.w;
    }

    float m[8], s[8];
    ull o2[4][4];
#pragma unroll
    for (int i = 0; i < 8; i++) s[i] = 0.f;
#pragma unroll
    for (int p = 0; p < 4; p++)
#pragma unroll
        for (int c = 0; c < 4; c++) o2[p][c] = 0ull;

#pragma unroll 1
    for (int cc = 0; cc < 3; cc++) {
        int kc = (cc == 0) ? k : (cc == 1 ? (k + KCHUNKS - 1) % KCHUNKS
                                          : (k + 1) % KCHUNKS);
        __syncthreads();
        for (int e = tid; e < 144*8; e += 288) {   // normalized keys transposed
            int j = e >> 3, q = e & 7;
            int tok = spb[kc*CHUNK + j] - h*LTOK;
            float4 v = *(const float4*)(xn + ((size_t)b*LTOK + tok)*CM + q*4);
            s_KT[(q*4+0)*144 + j] = v.x; s_KT[(q*4+1)*144 + j] = v.y;
            s_KT[(q*4+2)*144 + j] = v.z; s_KT[(q*4+3)*144 + j] = v.w;
        }
        for (int e = tid; e < 144*16; e += 288) {  // values
            int j = e >> 4, q = e & 15;
            int tok = spb[kc*CHUNK + j] - h*LTOK;
            float4 vv = *(const float4*)(ye + ((size_t)b*LTOK + tok)*COUT + q*4);
            *(float4*)(s_Y + j*64 + q*4) = vv;
        }
        __syncthreads();
        if (cc == 0) {
#pragma unroll
            for (int i = 0; i < 8; i++) m[i] = s_m[r0 + i];
        }

#pragma unroll 1
        for (int w = 0; w < 3; w++) {               // 48-key windows
            int kw0 = w*48;
            ull acc2[4][3];
#pragma unroll
            for (int p = 0; p < 4; p++)
#pragma unroll
                for (int j = 0; j < 3; j++) acc2[p][j] = 0ull;
#pragma unroll 2
            for (int f = 0; f < 32; f++) {
                ull qv[4];
#pragma unroll
                for (int p = 0; p < 4; p++)
                    qv[p] = *(const ull*)(s_QT + f*144 + r0 + 2*p);
#pragma unroll
                for (int j = 0; j < 3; j++) {
                    float kv = s_KT[f*144 + kw0 + jbase + j];
                    ull k2 = pk2(kv, kv);
#pragma unroll
                    for (int p = 0; p < 4; p++)
                        acc2[p][j] = ffma2(qv[p], k2, acc2[p][j]);
                }
            }
            // p = exp(|q|*(dot - 1)); no reductions, no rescale
            float a[8][3];
#pragma unroll
            for (int p = 0; p < 4; p++)
#pragma unroll
                for (int j = 0; j < 3; j++) upk2(acc2[p][j], a[2*p][j], a[2*p+1][j]);
#pragma unroll
            for (int i = 0; i < 8; i++) {
#pragma unroll
                for (int j = 0; j < 3; j++) {
                    float pv = __expf(fmaf(a[i][j], m[i], -m[i]));
                    a[i][j] = pv; s[i] += pv;
                }
            }
            __syncwarp();
#pragma unroll
            for (int j = 0; j < 3; j++)
#pragma unroll
                for (int p = 0; p < 4; p++)
                    s_P2[(ty*48 + jbase + j)*4 + p] = make_float2(a[2*p][j], a[2*p+1][j]);
            __syncwarp();
            // GEMM2: O += P*Y (packed over row pairs)
#pragma unroll 2
            for (int key = 0; key < 48; key++) {
                float4 y = *(const float4*)(s_Y + (kw0 + key)*64 + c0);
                ull yd[4] = { pk2(y.x,y.x), pk2(y.y,y.y), pk2(y.z,y.z), pk2(y.w,y.w) };
                const ull* pp = (const ull*)&s_P2[(ty*48 + key)*4];
#pragma unroll
                for (int p = 0; p < 4; p++) {
                    ull pv = pp[p];
#pragma unroll
                    for (int c = 0; c < 4; c++)
                        o2[p][c] = ffma2(pv, yd[c], o2[p][c]);
                }
            }
        }
    }

    // epilogue: one cross-thread sum reduction per row
#pragma unroll
    for (int i = 0; i < 8; i++) s[i] = gsum16(s[i]);
#pragma unroll
    for (int p = 0; p < 4; p++) {
        float lo[4], hi[4];
#pragma unroll
        for (int c = 0; c < 4; c++) upk2(o2[p][c], lo[c], hi[c]);
        float inv0 = 1.f / s[2*p], inv1 = 1.f / s[2*p+1];
        *(float4*)(ret + (((size_t)(b*NHASH + h))*LTOK + s_tq[r0+2*p  ])*COUT + c0) =
            make_float4(lo[0]*inv0, lo[1]*inv0, lo[2]*inv0, lo[3]*inv0);
        *(float4*)(ret + (((size_t)(b*NHASH + h))*LTOK + s_tq[r0+2*p+1])*COUT + c0) =
            make_float4(hi[0]*inv1, hi[1]*inv1, hi[2]*inv1, hi[3]*inv1);
    }
    if (tx == 0) {
#pragma unroll
        for (int i = 0; i < 8; i++)
            bs[((size_t)(b*NHASH + h))*LTOK + s_tq[r0+i]] = m[i] + __logf(s[i]);
    }
}

// ---------------- combine hash rounds + residual ---------------------------
__global__ void combine_kernel(const float* __restrict__ ret, const float* __restrict__ bs,
                               const float* __restrict__ resid, float* __restrict__ out) {
    int b = blockIdx.y, t0 = blockIdx.x*32;
    __shared__ float s_p[NHASH][32];
    __shared__ float s_tile[64][33];
    int tid = threadIdx.x;
    if (tid < 32) {
        int t = t0 + tid;
        float v0 = bs[((size_t)(b*NHASH+0))*LTOK + t];
        float v1 = bs[((size_t)(b*NHASH+1))*LTOK + t];
        float v2 = bs[((size_t)(b*NHASH+2))*LTOK + t];
        float v3 = bs[((size_t)(b*NHASH+3))*LTOK + t];
        float mm = fmaxf(fmaxf(v0,v1), fmaxf(v2,v3));
        float p0 = __expf(v0-mm), p1 = __expf(v1-mm), p2 = __expf(v2-mm), p3 = __expf(v3-mm);
        float inv = 1.f/(p0+p1+p2+p3);
        s_p[0][tid] = p0*inv; s_p[1][tid] = p1*inv; s_p[2][tid] = p2*inv; s_p[3][tid] = p3*inv;
    }
    __syncthreads();
    for (int e = tid; e < 2048; e += 256) {
        int c = e & 63, tl = e >> 6;
        int t = t0 + tl;
        float a = 0.f;
#pragma unroll
        for (int h = 0; h < NHASH; h++)
            a = fmaf(s_p[h][tl], ret[(((size_t)(b*NHASH + h))*LTOK + t)*COUT + c], a);
        s_tile[c][tl] = a;
    }
    __syncthreads();
    for (int e = tid; e < 2048; e += 256) {
        int tl = e & 31, c = e >> 5;
        size_t idx = ((size_t)(b*COUT + c))*LTOK + t0 + tl;
        out[idx] = s_tile[c][tl] + resid[idx];
    }
}

// ---------------- launch -----------------------------------------------------
extern "C" void kernel_launch(void* const* d_in, const int* in_sizes, int n_in,
                              void* d_out, int out_size) {
    const float* x   = (const float*)d_in[0];
    const float* w1  = (const float*)d_in[1];
    const float* b1  = (const float*)d_in[2];
    const float* w2  = (const float*)d_in[3];
    const float* b2  = (const float*)d_in[4];
    const float* wm  = (const float*)d_in[5];
    const float* bm  = (const float*)d_in[6];
    const float* wa  = (const float*)d_in[7];
    const float* ba  = (const float*)d_in[8];
    const float* rot = (const float*)d_in[9];
    float* out = (float*)d_out;

    float *up, *c1, *c2, *xe, *xn, *nrmp, *ye, *ret, *bsp;
    int *codes, *hist, *pref, *sorted;
    cudaGetSymbolAddress((void**)&up,    g_up);
    cudaGetSymbolAddress((void**)&c1,    g_c1);
    cudaGetSymbolAddress((void**)&c2,    g_c2);
    cudaGetSymbolAddress((void**)&xe,    g_xe);
    cudaGetSymbolAddress((void**)&xn,    g_xn);
    cudaGetSymbolAddress((void**)&nrmp,  g_nrm);
    cudaGetSymbolAddress((void**)&ye,    g_ye);
    cudaGetSymbolAddress((void**)&ret,   g_ret);
    cudaGetSymbolAddress((void**)&bsp,   g_bs);
    cudaGetSymbolAddress((void**)&codes, g_codes);
    cudaGetSymbolAddress((void**)&hist,  g_hist);
    cudaGetSymbolAddress((void**)&pref,  g_pref);
    cudaGetSymbolAddress((void**)&sorted,g_sorted);

    cudaFuncSetAttribute(attn_kernel, cudaFuncAttributeMaxDynamicSharedMemorySize, ATTN_SMEM);

    // 1. bicubic upsample
    upsample_kernel<<<(NB*CIN*HH*WW + 255)/256, 256>>>(x, up);
    // 2-3. conv3x3 + relu x2
    conv3x3_kernel<<<dim3(3,3,NB*8), 256>>>(up, w1, b1, c1, CIN,  COUT, 1, 0);
    conv3x3_kernel<<<dim3(3,3,NB*8), 256>>>(c1, w2, b2, c2, COUT, COUT, 1, 0);
    // 4. match conv -> x_embed token-major
    conv3x3_kernel<<<dim3(3,3,NB*4), 256>>>(c2, wm, bm, xe, COUT, CM, 0, 1);
    // 5. assembly 1x1 -> y_embed token-major
    conv1x1_kernel<<<dim3(LTOK/64, NB), 256>>>(c2, wa, ba, ye);
    // 6. LSH codes + normalized embeds + norms
    hash_kernel<<<NB*LTOK/128, 128>>>(xe, rot, codes, xn, nrmp);
    // 7. stable counting sort
    zero_hist_kernel<<<NB, 256>>>(hist);
    hist_kernel<<<(NB*LSORT + 255)/256, 256>>>(codes, hist);
    prefix_kernel<<<1, 32>>>(hist, pref);
    scatter_kernel<<<NB*TOTCODE/8, 256>>>(codes, pref, sorted);
    // 8. chunked attention
    attn_kernel<<<NB*NHASH*KCHUNKS, 288, ATTN_SMEM>>>(xn, nrmp, ye, sorted, ret, bsp);
    // 9. combine hash rounds + residual
    combine_kernel<<<dim3(LTOK/32, NB), 256>>>(ret, bsp, c2, out);
}

// round 17
// speedup vs baseline: 1.1271x; 1.0402x over previous
#include <cuda_runtime.h>
#include <cuda_bf16.h>
#include <math.h>

// Problem constants
#define NB    4
#define CIN   64
#define HIN   48
#define WIN   48
#define COUT  64
#define CM    32
#define HH    96
#define WW    96
#define LTOK  (HH*WW)     // 9216
#define NHASH 4
#define BUCK  64
#define CHUNK 144
#define KCHUNKS (LTOK/CHUNK)   // 64
#define TOTCODE 256
#define LSORT (NHASH*LTOK)     // 36864
#define FULLMASK 0xffffffffu

typedef unsigned long long ull;

// ---------------- f32x2 packed-math helpers (exact fp32, 2x throughput) ------
__device__ __forceinline__ ull pk2(float lo, float hi) {
    ull r; asm("mov.b64 %0, {%1, %2};" : "=l"(r) : "f"(lo), "f"(hi)); return r;
}
__device__ __forceinline__ void upk2(ull v, float& lo, float& hi) {
    asm("mov.b64 {%0, %1}, %2;" : "=f"(lo), "=f"(hi) : "l"(v));
}
__device__ __forceinline__ ull ffma2(ull a, ull b, ull c) {
    ull d; asm("fma.rn.f32x2 %0, %1, %2, %3;" : "=l"(d) : "l"(a), "l"(b), "l"(c)); return d;
}

// ---------------- device scratch ----------------
__device__ float g_up [NB*CIN*HH*WW];
__device__ float g_c1 [NB*COUT*HH*WW];
__device__ float g_c2 [NB*COUT*HH*WW];
__device__ float g_xe [NB*LTOK*CM];
__device__ float g_xn [NB*LTOK*CM];     // normalized x_embed (token-major)
__device__ float g_nrm[NB*LTOK];        // |x_embed| per token
__device__ float g_ye [NB*LTOK*COUT];
__device__ int   g_codes[NB*NHASH*LTOK];
__device__ int   g_hist [NB*TOTCODE];   // zero at load; scatter self-cleans
__device__ int   g_sorted[NB*LSORT];
__device__ float g_ret [NB*NHASH*LTOK*COUT];
__device__ float g_bs  [NB*NHASH*LTOK];

// ---------------- bicubic upsample ----------------
__device__ __forceinline__ float keysk(float x) {
    x = fabsf(x);
    if (x <= 1.f) return (1.5f*x - 2.5f)*x*x + 1.f;
    if (x <  2.f) return ((-0.5f*x + 2.5f)*x - 4.f)*x + 2.f;
    return 0.f;
}

__global__ void upsample_kernel(const float* __restrict__ in, float* __restrict__ out) {
    int g = blockIdx.x*256 + threadIdx.x;
    if (g >= NB*CIN*HH*WW) return;
    int ox = g % WW, oy = (g/WW) % HH, bc = g/(HH*WW);
    float sy = 0.5f*oy - 0.25f;
    float sx = 0.5f*ox - 0.25f;
    int iy0 = (int)floorf(sy) - 1;
    int ix0 = (int)floorf(sx) - 1;
    float wy[4], wx[4]; int iy[4], ix[4];
    float sumy = 0.f, sumx = 0.f;
#pragma unroll
    for (int j = 0; j < 4; j++) {
        int y = iy0 + j, x = ix0 + j;
        float wyv = (y >= 0 && y < HIN) ? keysk(sy - (float)y) : 0.f;
        float wxv = (x >= 0 && x < WIN) ? keysk(sx - (float)x) : 0.f;
        iy[j] = min(max(y,0), HIN-1); ix[j] = min(max(x,0), WIN-1);
        wy[j] = wyv; wx[j] = wxv; sumy += wyv; sumx += wxv;
    }
    float inv = 1.f/(sumy*sumx);
    const float* inp = in + (size_t)bc*HIN*WIN;
    float acc = 0.f;
#pragma unroll
    for (int jy = 0; jy < 4; jy++) {
        float row = 0.f;
#pragma unroll
        for (int jx = 0; jx < 4; jx++) row += wx[jx]*inp[iy[jy]*WIN + ix[jx]];
        acc += wy[jy]*row;
    }
    out[g] = acc*inv;
}

// -- 3x3 conv: 32x32 tile, 2x2 px/thread, 8 couts/block, half-stage prefetch -
#define STG   (4*1156)
#define WSTG  (4*8*9)

__global__ void __launch_bounds__(256, 2) conv3x3_kernel(
    const float* __restrict__ in, const float* __restrict__ w,
    const float* __restrict__ bias, float* __restrict__ out,
    int CIN_, int COUT_, int relu, int token_major) {
    const int CPB = 8;
    int groups = COUT_/CPB;
    int z  = blockIdx.z;
    int cg = z % groups;
    int b  = z / groups;
    int tid = threadIdx.x;
    int tx = tid & 15, ty = tid >> 4;
    int ox0 = blockIdx.x*32, oy0 = blockIdx.y*32;
    __shared__ float s_in[2][STG];
    __shared__ float s_w[2][WSTG];

    int offc[5];
#pragma unroll
    for (int j = 0; j < 5; j++) {
        int e = tid + j*256;
        bool slot = (j < 4) || (tid < 132);
        int ly = e/34, lx = e - ly*34;
        int iy = oy0-1+ly, ix = ox0-1+lx;
        bool ok = slot && iy >= 0 && iy < HH && ix >= 0 && ix < WW;
        offc[j] = ok ? (iy*WW + ix) : -1;
    }
    int wb0, wb1;
    {
        int e = tid;
        int ch = e/72, rem = e - ch*72, co = rem/9, kk = rem - co*9;
        wb0 = ((cg*CPB+co)*CIN_ + ch)*9 + kk;
        e = 256 + tid;
        ch = e/72; rem = e - ch*72; co = rem/9; kk = rem - co*9;
        wb1 = ((cg*CPB+co)*CIN_ + ch)*9 + kk;
    }
    const float* inb = in + (size_t)b*CIN_*HH*WW;

    float acc[CPB][4];
#pragma unroll
    for (int i = 0; i < CPB; i++)
#pragma unroll
        for (int p = 0; p < 4; p++) acc[i][p] = 0.f;

    {
#pragma unroll
        for (int ch = 0; ch < 4; ch++) {
            const float* inps = inb + (size_t)ch*HH*WW;
#pragma unroll
            for (int j = 0; j < 5; j++) {
                if (j < 4 || tid < 132)
                    s_in[0][ch*1156 + tid + j*256] = (offc[j] >= 0) ? inps[offc[j]] : 0.f;
            }
        }
        s_w[0][tid] = w[wb0];
        if (tid < 32) s_w[0][256+tid] = w[wb1];
    }
    __syncthreads();

    for (int s = 0; s < CIN_; s += 4) {
        int cur = (s >> 2) & 1;
        bool more = (s + 4 < CIN_);
        float r[10]; float rw0 = 0.f, rw1 = 0.f;

        if (more) {
            const float* inps = inb + (size_t)(s+4)*HH*WW;
#pragma unroll
            for (int ch = 0; ch < 2; ch++)
#pragma unroll
                for (int j = 0; j < 5; j++)
                    r[ch*5+j] = (offc[j] >= 0 && (j < 4 || tid < 132))
                              ? inps[(size_t)ch*HH*WW + offc[j]] : 0.f;
            rw0 = w[wb0 + (s+4)*9];
            if (tid < 32) rw1 = w[wb1 + (s+4)*9];
        }
#pragma unroll
        for (int ch = 0; ch < 2; ch++) {
            float win[4][4];
            const float* base = s_in[cur] + ch*1156 + (2*ty)*34 + 2*tx;
#pragma unroll
            for (int rr = 0; rr < 4; rr++) {
                float2 a = *(const float2*)(base + rr*34);
                float2 bq = *(const float2*)(base + rr*34 + 2);
                win[rr][0] = a.x; win[rr][1] = a.y; win[rr][2] = bq.x; win[rr][3] = bq.y;
            }
            const float* wp = s_w[cur] + ch*CPB*9;
#pragma unroll
            for (int co = 0; co < CPB; co++) {
                float wr[9];
#pragma unroll
                for (int kk = 0; kk < 9; kk++) wr[kk] = wp[co*9+kk];
#pragma unroll
                for (int rr = 0; rr < 2; rr++)
#pragma unroll
                    for (int c = 0; c < 2; c++) {
                        float a = acc[co][rr*2+c];
#pragma unroll
                        for (int ky = 0; ky < 3; ky++)
#pragma unroll
                            for (int kx = 0; kx < 3; kx++)
                                a = fmaf(win[rr+ky][c+kx], wr[ky*3+kx], a);
                        acc[co][rr*2+c] = a;
                    }
            }
        }
        if (more) {
            float* dst = s_in[cur^1];
#pragma unroll
            for (int ch = 0; ch < 2; ch++)
#pragma unroll
                for (int j = 0; j < 5; j++)
                    if (j < 4 || tid < 132) dst[ch*1156 + tid + j*256] = r[ch*5+j];
            const float* inps = inb + (size_t)(s+4)*HH*WW;
#pragma unroll
            for (int ch = 0; ch < 2; ch++)
#pragma unroll
                for (int j = 0; j < 5; j++)
                    r[ch*5+j] = (offc[j] >= 0 && (j < 4 || tid < 132))
                              ? inps[(size_t)(ch+2)*HH*WW + offc[j]] : 0.f;
        }
#pragma unroll
        for (int ch = 2; ch < 4; ch++) {
            float win[4][4];
            const float* base = s_in[cur] + ch*1156 + (2*ty)*34 + 2*tx;
#pragma unroll
            for (int rr = 0; rr < 4; rr++) {
                float2 a = *(const float2*)(base + rr*34);
                float2 bq = *(const float2*)(base + rr*34 + 2);
                win[rr][0] = a.x; win[rr][1] = a.y; win[rr][2] = bq.x; win[rr][3] = bq.y;
            }
            const float* wp = s_w[cur] + ch*CPB*9;
#pragma unroll
            for (int co = 0; co < CPB; co++) {
                float wr[9];
#pragma unroll
                for (int kk = 0; kk < 9; kk++) wr[kk] = wp[co*9+kk];
#pragma unroll
                for (int rr = 0; rr < 2; rr++)
#pragma unroll
                    for (int c = 0; c < 2; c++) {
                        float a = acc[co][rr*2+c];
#pragma unroll
                        for (int ky = 0; ky < 3; ky++)
#pragma unroll
                            for (int kx = 0; kx < 3; kx++)
                                a = fmaf(win[rr+ky][c+kx], wr[ky*3+kx], a);
                        acc[co][rr*2+c] = a;
                    }
            }
        }
        if (more) {
            float* dst = s_in[cur^1];
#pragma unroll
            for (int ch = 0; ch < 2; ch++)
#pragma unroll
                for (int j = 0; j < 5; j++)
                    if (j < 4 || tid < 132) dst[(ch+2)*1156 + tid + j*256] = r[ch*5+j];
            s_w[cur^1][tid] = rw0;
            if (tid < 32) s_w[cur^1][256+tid] = rw1;
        }
        __syncthreads();
    }
#pragma unroll
    for (int co = 0; co < CPB; co++) {
        int cout = cg*CPB + co;
        float bv = bias[cout];
#pragma unroll
        for (int rr = 0; rr < 2; rr++) {
            float v0 = acc[co][rr*2+0] + bv;
            float v1 = acc[co][rr*2+1] + bv;
            if (relu) { v0 = fmaxf(v0, 0.f); v1 = fmaxf(v1, 0.f); }
            int row = oy0 + 2*ty + rr, col = ox0 + 2*tx;
            if (token_major) {
                out[((size_t)b*LTOK + row*WW + col    )*COUT_ + cout] = v0;
                out[((size_t)b*LTOK + row*WW + col + 1)*COUT_ + cout] = v1;
            } else {
                *(float2*)&out[((size_t)(b*COUT_+cout))*LTOK + row*WW + col] =
                    make_float2(v0, v1);
            }
        }
    }
}

// ---- 1x1 conv -> y_embed [b][t][64], register-tiled 4co x 4tt per thread ---
__global__ void __launch_bounds__(256) conv1x1_kernel(
    const float* __restrict__ in, const float* __restrict__ w,
    const float* __restrict__ bias, float* __restrict__ out) {
    int b  = blockIdx.y;
    int t0 = blockIdx.x*64;
    __shared__ float s_x[64][64];   // [ci][tt], both dims contiguous in 4s
    __shared__ float s_w[64][64];   // [ci][co]
    int tid = threadIdx.x;
    for (int e = tid; e < 64*64; e += 256) {
        int ci = e >> 6, tt = e & 63;
        s_x[ci][tt] = in[((size_t)(b*COUT+ci))*LTOK + t0 + tt];
        s_w[ci][tt] = w[tt*64 + ci];    // tt acts as co here
    }
    __syncthreads();
    int co0 = (tid & 15)*4;
    int tt0 = (tid >> 4)*4;
    float acc[4][4];                 // [tt][co]
    float bv0 = bias[co0], bv1 = bias[co0+1], bv2 = bias[co0+2], bv3 = bias[co0+3];
#pragma unroll
    for (int t = 0; t < 4; t++) {
        acc[t][0] = bv0; acc[t][1] = bv1; acc[t][2] = bv2; acc[t][3] = bv3;
    }
#pragma unroll 8
    for (int ci = 0; ci < 64; ci++) {
        float4 xv = *(const float4*)&s_x[ci][tt0];
        float4 wv = *(const float4*)&s_w[ci][co0];
        float xs[4] = { xv.x, xv.y, xv.z, xv.w };
        float ws[4] = { wv.x, wv.y, wv.z, wv.w };
#pragma unroll
        for (int t = 0; t < 4; t++)
#pragma unroll
            for (int c = 0; c < 4; c++)
                acc[t][c] = fmaf(xs[t], ws[c], acc[t][c]);
    }
#pragma unroll
    for (int t = 0; t < 4; t++)
        *(float4*)&out[((size_t)b*LTOK + t0 + tt0 + t)*COUT + co0] =
            make_float4(acc[t][0], acc[t][1], acc[t][2], acc[t][3]);
}

// ------ LSH hashing (f32x2) + emit normalized x_embed and norms -------------
__global__ void hash_kernel(const float* __restrict__ xe, const float* __restrict__ rot,
                            int* __restrict__ codes,
                            float* __restrict__ xn, float* __restrict__ nrm_out) {
    __shared__ __align__(16) float s_rot[CM*NHASH*32];
    int tid = threadIdx.x;
    for (int e = tid; e < CM*NHASH*32; e += 128) s_rot[e] = rot[e];
    __syncthreads();
    int g = blockIdx.x*128 + tid;
    float xf[CM];
    const float* xp = xe + (size_t)g*CM;
#pragma unroll
    for (int f = 0; f < CM; f++) xf[f] = xp[f];
    {
        float ss = 0.f;
#pragma unroll
        for (int f = 0; f < CM; f++) ss = fmaf(xf[f], xf[f], ss);
        float nrm = sqrtf(ss);
        nrm_out[g] = nrm;
        float inv = 1.f / fmaxf(nrm, 5e-5f);
        float* op = xn + (size_t)g*CM;
#pragma unroll
        for (int q = 0; q < 8; q++)
            *(float4*)(op + q*4) = make_float4(xf[q*4+0]*inv, xf[q*4+1]*inv,
                                               xf[q*4+2]*inv, xf[q*4+3]*inv);
    }
    int b = g / LTOK, t = g % LTOK;
    for (int h = 0; h < NHASH; h++) {
        ull acc2[16];
#pragma unroll
        for (int i = 0; i < 16; i++) acc2[i] = 0ull;
#pragma unroll 4
        for (int f = 0; f < CM; f++) {
            ull x2 = pk2(xf[f], xf[f]);
            const ull* rp = (const ull*)&s_rot[(f*NHASH + h)*32];
#pragma unroll
            for (int i = 0; i < 16; i++) acc2[i] = ffma2(x2, rp[i], acc2[i]);
        }
        float sv[32];
#pragma unroll
        for (int i = 0; i < 16; i++) upk2(acc2[i], sv[2*i], sv[2*i+1]);
        float bv = sv[0]; int bi = 0;
#pragma unroll
        for (int i = 1; i < 32; i++) if (sv[i] > bv) { bv = sv[i]; bi = i; }
#pragma unroll
        for (int i = 0; i < 32; i++) if (-sv[i] > bv) { bv = -sv[i]; bi = 32 + i; }
        codes[((size_t)(b*NHASH + h))*LTOK + t] = h*BUCK + bi;
    }
}

// ---------------- counting sort (hist + fused-prefix scatter) ---------------
__global__ void hist_kernel(const int* __restrict__ codes, int* __restrict__ hist) {
    int g = blockIdx.x*256 + threadIdx.x;
    if (g < NB*LSORT) {
        int b = g / LSORT;
        atomicAdd(&hist[b*TOTCODE + codes[g]], 1);
    }
}

// scatter: per-warp inline prefix over hist, then stable ballot compaction.
// After use, each warp zeroes its own hist entry (self-clean for next launch).
__global__ void scatter_kernel(const int* __restrict__ codes, int* __restrict__ hist,
                               int* __restrict__ sorted_p) {
    int wid  = (blockIdx.x*blockDim.x + threadIdx.x) >> 5;
    int lane = threadIdx.x & 31;
    if (wid >= NB*TOTCODE) return;
    int b = wid >> 8, c = wid & 255;
    int h = c >> 6;
    // inline exclusive prefix: sum hist[b][c'] for c' < c
    int base = 0;
    for (int cc = lane; cc < c; cc += 32) base += hist[b*TOTCODE + cc];
#pragma unroll
    for (int d = 16; d > 0; d >>= 1) base += __shfl_xor_sync(FULLMASK, base, d);
    const int* cp = codes + ((size_t)(b*NHASH + h))*LTOK;
    int off = 0;
    for (int t0 = 0; t0 < LTOK; t0 += 32) {
        int t = t0 + lane;
        bool m = (cp[t] == c);
        unsigned mask = __ballot_sync(FULLMASK, m);
        if (m) {
            int pos = base + off + __popc(mask & ((1u << lane) - 1u));
            sorted_p[(size_t)b*LSORT + pos] = h*LTOK + t;
        }
        off += __popc(mask);
    }
    if (lane == 0) hist[b*TOTCODE + c] = 0;   // self-clean for next launch
}

// ---- chunked attention: prenormalized keys/queries, m = |q| known ----------
// smem: KT[32*144] | QT[32*144] | Y[144*64] | P2[18][48][4]float2 | tq | nrm
#define ATTN_SMEM ((32*144*2 + 144*64)*4 + 18*48*4*8 + 144*4 + 144*4)

__device__ __forceinline__ float gsum16(float v) {
    v += __shfl_xor_sync(FULLMASK, v, 1);
    v += __shfl_xor_sync(FULLMASK, v, 2);
    v += __shfl_xor_sync(FULLMASK, v, 4);
    v += __shfl_xor_sync(FULLMASK, v, 8);
    return v;
}

__global__ void __launch_bounds__(288, 2) attn_kernel(
    const float* __restrict__ xn, const float* __restrict__ nrm,
    const float* __restrict__ ye,
    const int* __restrict__ sorted_p, float* __restrict__ ret, float* __restrict__ bs) {
    extern __shared__ float sm[];
    float*  s_KT = sm;
    float*  s_QT = s_KT + 32*144;
    float*  s_Y  = s_QT + 32*144;
    float2* s_P2 = (float2*)(s_Y + 144*64);
    int*    s_tq = (int*)(s_P2 + 18*48*4);
    float*  s_m  = (float*)(s_tq + 144);

    int blk = blockIdx.x;
    int k = blk & 63, h = (blk >> 6) & 3, b = blk >> 8;
    int tid = threadIdx.x;
    int tx = tid & 15, ty = tid >> 4;
    int r0 = ty*8, c0 = tx*4, jbase = tx*3;
    const int* spb = sorted_p + (size_t)b*LSORT + h*LTOK;

    if (tid < 144)
        s_tq[tid] = spb[k*CHUNK + tid] - h*LTOK;
    __syncthreads();
    if (tid < 144)
        s_m[tid] = nrm[(size_t)b*LTOK + s_tq[tid]];
    for (int e = tid; e < 144*8; e += 288) {
        int j = e >> 3, q = e & 7;
        float4 v = *(const float4*)(xn + ((size_t)b*LTOK + s_tq[j])*CM + q*4);
        s_QT[(q*4+0)*144 + j] = v.x; s_QT[(q*4+1)*144 + j] = v.y;
        s_QT[(q*4+2)*144 + j] = v.z; s_QT[(q*4+3)*144 + j] = v.w;
    }

    float m[8], s[8];
    ull o2[4][4];
#pragma unroll
    for (int i = 0; i < 8; i++) s[i] = 0.f;
#pragma unroll
    for (int p = 0; p < 4; p++)
#pragma unroll
        for (int c = 0; c < 4; c++) o2[p][c] = 0ull;

#pragma unroll 1
    for (int cc = 0; cc < 3; cc++) {
        int kc = (cc == 0) ? k : (cc == 1 ? (k + KCHUNKS - 1) % KCHUNKS
                                          : (k + 1) % KCHUNKS);
        __syncthreads();
        for (int e = tid; e < 144*8; e += 288) {
            int j = e >> 3, q = e & 7;
            int tok = spb[kc*CHUNK + j] - h*LTOK;
            float4 v = *(const float4*)(xn + ((size_t)b*LTOK + tok)*CM + q*4);
            s_KT[(q*4+0)*144 + j] = v.x; s_KT[(q*4+1)*144 + j] = v.y;
            s_KT[(q*4+2)*144 + j] = v.z; s_KT[(q*4+3)*144 + j] = v.w;
        }
        for (int e = tid; e < 144*16; e += 288) {
            int j = e >> 4, q = e & 15;
            int tok = spb[kc*CHUNK + j] - h*LTOK;
            float4 vv = *(const float4*)(ye + ((size_t)b*LTOK + tok)*COUT + q*4);
            *(float4*)(s_Y + j*64 + q*4) = vv;
        }
        __syncthreads();
        if (cc == 0) {
#pragma unroll
            for (int i = 0; i < 8; i++) m[i] = s_m[r0 + i];
        }

#pragma unroll 1
        for (int w = 0; w < 3; w++) {
            int kw0 = w*48;
            ull acc2[4][3];
#pragma unroll
            for (int p = 0; p < 4; p++)
#pragma unroll
                for (int j = 0; j < 3; j++) acc2[p][j] = 0ull;
#pragma unroll 2
            for (int f = 0; f < 32; f++) {
                ull qv[4];
#pragma unroll
                for (int p = 0; p < 4; p++)
                    qv[p] = *(const ull*)(s_QT + f*144 + r0 + 2*p);
#pragma unroll
                for (int j = 0; j < 3; j++) {
                    float kv = s_KT[f*144 + kw0 + jbase + j];
                    ull k2 = pk2(kv, kv);
#pragma unroll
                    for (int p = 0; p < 4; p++)
                        acc2[p][j] = ffma2(qv[p], k2, acc2[p][j]);
                }
            }
            float a[8][3];
#pragma unroll
            for (int p = 0; p < 4; p++)
#pragma unroll
                for (int j = 0; j < 3; j++) upk2(acc2[p][j], a[2*p][j], a[2*p+1][j]);
#pragma unroll
            for (int i = 0; i < 8; i++) {
#pragma unroll
                for (int j = 0; j < 3; j++) {
                    float pv = __expf(fmaf(a[i][j], m[i], -m[i]));
                    a[i][j] = pv; s[i] += pv;
                }
            }
            __syncwarp();
#pragma unroll
            for (int j = 0; j < 3; j++)
#pragma unroll
                for (int p = 0; p < 4; p++)
                    s_P2[(ty*48 + jbase + j)*4 + p] = make_float2(a[2*p][j], a[2*p+1][j]);
            __syncwarp();
#pragma unroll 2
            for (int key = 0; key < 48; key++) {
                float4 y = *(const float4*)(s_Y + (kw0 + key)*64 + c0);
                ull yd[4] = { pk2(y.x,y.x), pk2(y.y,y.y), pk2(y.z,y.z), pk2(y.w,y.w) };
                const ull* pp = (const ull*)&s_P2[(ty*48 + key)*4];
#pragma unroll
                for (int p = 0; p < 4; p++) {
                    ull pv = pp[p];
#pragma unroll
                    for (int c = 0; c < 4; c++)
                        o2[p][c] = ffma2(pv, yd[c], o2[p][c]);
                }
            }
        }
    }

#pragma unroll
    for (int i = 0; i < 8; i++) s[i] = gsum16(s[i]);
#pragma unroll
    for (int p = 0; p < 4; p++) {
        float lo[4], hi[4];
#pragma unroll
        for (int c = 0; c < 4; c++) upk2(o2[p][c], lo[c], hi[c]);
        float inv0 = 1.f / s[2*p], inv1 = 1.f / s[2*p+1];
        *(float4*)(ret + (((size_t)(b*NHASH + h))*LTOK + s_tq[r0+2*p  ])*COUT + c0) =
            make_float4(lo[0]*inv0, lo[1]*inv0, lo[2]*inv0, lo[3]*inv0);
        *(float4*)(ret + (((size_t)(b*NHASH + h))*LTOK + s_tq[r0+2*p+1])*COUT + c0) =
            make_float4(hi[0]*inv1, hi[1]*inv1, hi[2]*inv1, hi[3]*inv1);
    }
    if (tx == 0) {
#pragma unroll
        for (int i = 0; i < 8; i++)
            bs[((size_t)(b*NHASH + h))*LTOK + s_tq[r0+i]] = m[i] + __logf(s[i]);
    }
}

// ---------------- combine hash rounds + residual ---------------------------
__global__ void combine_kernel(const float* __restrict__ ret, const float* __restrict__ bs,
                               const float* __restrict__ resid, float* __restrict__ out) {
    int b = blockIdx.y, t0 = blockIdx.x*32;
    __shared__ float s_p[NHASH][32];
    __shared__ float s_tile[64][33];
    int tid = threadIdx.x;
    if (tid < 32) {
        int t = t0 + tid;
        float v0 = bs[((size_t)(b*NHASH+0))*LTOK + t];
        float v1 = bs[((size_t)(b*NHASH+1))*LTOK + t];
        float v2 = bs[((size_t)(b*NHASH+2))*LTOK + t];
        float v3 = bs[((size_t)(b*NHASH+3))*LTOK + t];
        float mm = fmaxf(fmaxf(v0,v1), fmaxf(v2,v3));
        float p0 = __expf(v0-mm), p1 = __expf(v1-mm), p2 = __expf(v2-mm), p3 = __expf(v3-mm);
        float inv = 1.f/(p0+p1+p2+p3);
        s_p[0][tid] = p0*inv; s_p[1][tid] = p1*inv; s_p[2][tid] = p2*inv; s_p[3][tid] = p3*inv;
    }
    __syncthreads();
    for (int e = tid; e < 2048; e += 256) {
        int c = e & 63, tl = e >> 6;
        int t = t0 + tl;
        float a = 0.f;
#pragma unroll
        for (int h = 0; h < NHASH; h++)
            a = fmaf(s_p[h][tl], ret[(((size_t)(b*NHASH + h))*LTOK + t)*COUT + c], a);
        s_tile[c][tl] = a;
    }
    __syncthreads();
    for (int e = tid; e < 2048; e += 256) {
        int tl = e & 31, c = e >> 5;
        size_t idx = ((size_t)(b*COUT + c))*LTOK + t0 + tl;
        out[idx] = s_tile[c][tl] + resid[idx];
    }
}

// ---------------- launch -----------------------------------------------------
extern "C" void kernel_launch(void* const* d_in, const int* in_sizes, int n_in,
                              void* d_out, int out_size) {
    const float* x   = (const float*)d_in[0];
    const float* w1  = (const float*)d_in[1];
    const float* b1  = (const float*)d_in[2];
    const float* w2  = (const float*)d_in[3];
    const float* b2  = (const float*)d_in[4];
    const float* wm  = (const float*)d_in[5];
    const float* bm  = (const float*)d_in[6];
    const float* wa  = (const float*)d_in[7];
    const float* ba  = (const float*)d_in[8];
    const float* rot = (const float*)d_in[9];
    float* out = (float*)d_out;

    float *up, *c1, *c2, *xe, *xn, *nrmp, *ye, *ret, *bsp;
    int *codes, *hist, *sorted;
    cudaGetSymbolAddress((void**)&up,    g_up);
    cudaGetSymbolAddress((void**)&c1,    g_c1);
    cudaGetSymbolAddress((void**)&c2,    g_c2);
    cudaGetSymbolAddress((void**)&xe,    g_xe);
    cudaGetSymbolAddress((void**)&xn,    g_xn);
    cudaGetSymbolAddress((void**)&nrmp,  g_nrm);
    cudaGetSymbolAddress((void**)&ye,    g_ye);
    cudaGetSymbolAddress((void**)&ret,   g_ret);
    cudaGetSymbolAddress((void**)&bsp,   g_bs);
    cudaGetSymbolAddress((void**)&codes, g_codes);
    cudaGetSymbolAddress((void**)&hist,  g_hist);
    cudaGetSymbolAddress((void**)&sorted,g_sorted);

    cudaFuncSetAttribute(attn_kernel, cudaFuncAttributeMaxDynamicSharedMemorySize, ATTN_SMEM);

    // 1. bicubic upsample
    upsample_kernel<<<(NB*CIN*HH*WW + 255)/256, 256>>>(x, up);
    // 2-3. conv3x3 + relu x2
    conv3x3_kernel<<<dim3(3,3,NB*8), 256>>>(up, w1, b1, c1, CIN,  COUT, 1, 0);
    conv3x3_kernel<<<dim3(3,3,NB*8), 256>>>(c1, w2, b2, c2, COUT, COUT, 1, 0);
    // 4. match conv -> x_embed token-major
    conv3x3_kernel<<<dim3(3,3,NB*4), 256>>>(c2, wm, bm, xe, COUT, CM, 0, 1);
    // 5. assembly 1x1 -> y_embed token-major (register-tiled)
    conv1x1_kernel<<<dim3(LTOK/64, NB), 256>>>(c2, wa, ba, ye);
    // 6. LSH codes + normalized embeds + norms
    hash_kernel<<<NB*LTOK/128, 128>>>(xe, rot, codes, xn, nrmp);
    // 7. stable counting sort (hist + fused-prefix self-cleaning scatter)
    hist_kernel<<<(NB*LSORT + 255)/256, 256>>>(codes, hist);
    scatter_kernel<<<NB*TOTCODE/8, 256>>>(codes, hist, sorted);
    // 8. chunked attention
    attn_kernel<<<NB*NHASH*KCHUNKS, 288, ATTN_SMEM>>>(xn, nrmp, ye, sorted, ret, bsp);
    // 9. combine hash rounds + residual
    combine_kernel<<<dim3(LTOK/32, NB), 256>>>(ret, bsp, c2, out);
}